// round 1
// baseline (speedup 1.0000x reference)
#include <cuda_runtime.h>
#include <math.h>

// Problem constants (fixed shapes)
#define Dd 1024
#define Aa 16
#define Cc 8
#define DCc 64
#define CDd 512      // C*dc
#define E2 128       // 2*dc
#define TB 32        // tokens per CTA in token_kernel
#define NMAX 32768

// -------- device scratch (no allocations allowed) --------
__device__ __align__(16) float g_an[Aa * Dd];        // l2-normalized anchors
__device__ __align__(16) float g_gatesig[Dd];        // sigmoid(gate)
__device__ __align__(16) float g_Y[(size_t)NMAX * CDd]; // 64 MB: y_flat

// -------- f32x2 packed helpers (Blackwell) --------
__device__ __forceinline__ void ffma2(unsigned long long &d, unsigned long long a, unsigned long long b) {
    asm("fma.rn.f32x2 %0, %1, %2, %0;" : "+l"(d) : "l"(a), "l"(b));
}
__device__ __forceinline__ unsigned long long dup2(float v) {
    unsigned long long r; asm("mov.b64 %0, {%1, %1};" : "=l"(r) : "f"(v)); return r;
}
__device__ __forceinline__ float2 unpk(unsigned long long v) {
    float2 r; asm("mov.b64 {%0, %1}, %2;" : "=f"(r.x), "=f"(r.y) : "l"(v)); return r;
}

__device__ __forceinline__ float wsum(float v) {
#pragma unroll
    for (int o = 16; o; o >>= 1) v += __shfl_xor_sync(0xffffffffu, v, o);
    return v;
}

// ================= K0: prep anchors + gate =================
__global__ void prep_kernel(const float* __restrict__ anchors, const float* __restrict__ gate) {
    int tid = threadIdx.x, lane = tid & 31, wid = tid >> 5;
    __shared__ float red[8];
    if (blockIdx.x < Aa) {
        int j = blockIdx.x;
        float s = 0.f;
        // 256 threads, 4 elems each
        float4 v = *(const float4*)(anchors + j * Dd + tid * 4);
        s = v.x * v.x + v.y * v.y + v.z * v.z + v.w * v.w;
        s = wsum(s);
        if (lane == 0) red[wid] = s;
        __syncthreads();
        if (wid == 0) {
            float t = (lane < 8) ? red[lane] : 0.f;
            t = wsum(t);
            if (lane == 0) red[0] = t;
        }
        __syncthreads();
        float inv = 1.0f / fmaxf(sqrtf(red[0]), 1e-12f);
        float4 o = make_float4(v.x * inv, v.y * inv, v.z * inv, v.w * inv);
        *(float4*)(g_an + j * Dd + tid * 4) = o;
    } else {
        for (int i = tid; i < Dd; i += 256)
            g_gatesig[i] = 1.0f / (1.0f + expf(-gate[i]));
    }
}

// ================= K1: per-token LN/L2/dots + per-comp MLP + LN =================
// smem layout (floats):
#define OFF_AN   0        // phase A: 16384 (anchors) ; phase B reuses this region:
#define OFF_W2   0        //   8192  (W2[k] 128x64)
#define OFF_U    8192     //   4096  (u 32x128)
#define OFF_YB   12288    //   2048  (y 32x64)
#define OFF_W1   16384    //   2048
#define OFF_B1   18432    //   1024
#define OFF_B2   19456    //   512
#define OFF_CG   19968    //   512
#define OFF_CB   20480    //   512
#define OFF_TRI  20992    //   512 (32x16)
#define OFF_LNG  21504    //   1024
#define OFF_LNB  22528    //   1024
#define SM_FLOATS 23552   // 94208 bytes

__global__ void __launch_bounds__(256, 2)
token_kernel(const float* __restrict__ x,
             const float* __restrict__ ln_g, const float* __restrict__ ln_b,
             const float* __restrict__ W1, const float* __restrict__ b1,
             const float* __restrict__ W2, const float* __restrict__ b2,
             const float* __restrict__ cg, const float* __restrict__ cb)
{
    extern __shared__ float sm[];
    const int tid = threadIdx.x, lane = tid & 31, wid = tid >> 5;

    // cooperative loads of constants
    for (int t = tid; t < 4096; t += 256)
        *(float4*)&sm[OFF_AN + t * 4] = *(const float4*)&g_an[t * 4];
    for (int t = tid; t < 512; t += 256)
        *(float4*)&sm[OFF_W1 + t * 4] = *(const float4*)&W1[t * 4];
    *(float4*)&sm[OFF_B1 + tid * 4] = *(const float4*)&b1[tid * 4];
    if (tid < 128) {
        *(float4*)&sm[OFF_B2 + tid * 4] = *(const float4*)&b2[tid * 4];
        *(float4*)&sm[OFF_CG + tid * 4] = *(const float4*)&cg[tid * 4];
        *(float4*)&sm[OFF_CB + tid * 4] = *(const float4*)&cb[tid * 4];
    }
    *(float4*)&sm[OFF_LNG + tid * 4] = *(const float4*)&ln_g[tid * 4];
    *(float4*)&sm[OFF_LNB + tid * 4] = *(const float4*)&ln_b[tid * 4];
    __syncthreads();

    const long base_tok = (long)blockIdx.x * TB;

    // ---------- Phase A: warp-per-token LN + L2 + 16 anchor dots ----------
    for (int r = 0; r < TB / 8; ++r) {
        const int n = r * 8 + wid;
        const float* xr = x + (base_tok + n) * (long)Dd;
        float v[32];
#pragma unroll
        for (int q = 0; q < 8; ++q) {
            float4 t4 = *(const float4*)(xr + q * 128 + lane * 4);
            v[q * 4 + 0] = t4.x; v[q * 4 + 1] = t4.y; v[q * 4 + 2] = t4.z; v[q * 4 + 3] = t4.w;
        }
        float s = 0.f;
#pragma unroll
        for (int i = 0; i < 32; ++i) s += v[i];
        s = wsum(s);
        const float mu = s * (1.0f / Dd);
        float vs = 0.f;
#pragma unroll
        for (int i = 0; i < 32; ++i) { float dd = v[i] - mu; vs += dd * dd; }
        vs = wsum(vs);
        const float rstd = rsqrtf(vs * (1.0f / Dd) + 1e-5f);
        // LN into v, accumulate ||LN||^2
        float n2 = 0.f;
#pragma unroll
        for (int q = 0; q < 8; ++q) {
            float4 gv = *(const float4*)&sm[OFF_LNG + q * 128 + lane * 4];
            float4 bv = *(const float4*)&sm[OFF_LNB + q * 128 + lane * 4];
            float a0 = (v[q*4+0] - mu) * rstd * gv.x + bv.x;
            float a1 = (v[q*4+1] - mu) * rstd * gv.y + bv.y;
            float a2 = (v[q*4+2] - mu) * rstd * gv.z + bv.z;
            float a3 = (v[q*4+3] - mu) * rstd * gv.w + bv.w;
            v[q*4+0] = a0; v[q*4+1] = a1; v[q*4+2] = a2; v[q*4+3] = a3;
            n2 += a0 * a0 + a1 * a1 + a2 * a2 + a3 * a3;
        }
        n2 = wsum(n2);
        const float inv = 1.0f / fmaxf(sqrtf(n2), 1e-12f);
        // 16 dots with normalized anchors
        float acc[16];
#pragma unroll
        for (int j = 0; j < 16; ++j) acc[j] = 0.f;
#pragma unroll
        for (int q = 0; q < 8; ++q) {
#pragma unroll
            for (int j = 0; j < 16; ++j) {
                float4 a4 = *(const float4*)&sm[OFF_AN + j * Dd + q * 128 + lane * 4];
                acc[j] += v[q*4+0] * a4.x + v[q*4+1] * a4.y + v[q*4+2] * a4.z + v[q*4+3] * a4.w;
            }
        }
#pragma unroll
        for (int j = 0; j < 16; ++j) {
            float aj = wsum(acc[j]);
            if (lane == 0) sm[OFF_TRI + n * 16 + j] = 1.0f - aj * inv;
        }
    }

    // ---------- Phase B: per-compartment MLP + y-GEMM + per-comp LN ----------
    const int td = tid & 15;          // d quad: d = td*4..td*4+3
    const int tpair = tid >> 4;       // token pair: 2*tpair, 2*tpair+1

    for (int k = 0; k < Cc; ++k) {
        __syncthreads();  // protect reused region (anchors on k=0, y/u/W2 otherwise)
        // load W2[k] (128x64 f32)
        const float4* w2g = (const float4*)(W2 + k * (E2 * DCc));
        for (int t = tid; t < 2048; t += 256)
            *(float4*)&sm[OFF_W2 + t * 4] = w2g[t];
        // compute u[n][e] = relu(g0*W1[k,0,e] + g1*W1[k,1,e] + b1)^2
        for (int t = tid; t < TB * E2; t += 256) {
            int n = t >> 7, e = t & 127;
            float uu = sm[OFF_TRI + n * 16 + k]     * sm[OFF_W1 + (k * 2 + 0) * E2 + e]
                     + sm[OFF_TRI + n * 16 + 8 + k] * sm[OFF_W1 + (k * 2 + 1) * E2 + e]
                     + sm[OFF_B1 + k * E2 + e];
            uu = fmaxf(uu, 0.0f);
            sm[OFF_U + t] = uu * uu;
        }
        __syncthreads();
        // GEMM 32(tokens) x 64(d) x 128(e), f32x2 packed
        const int n0 = 2 * tpair, n1 = n0 + 1;
        unsigned long long a00 = 0ull, a01 = 0ull, a10 = 0ull, a11 = 0ull;
#pragma unroll 4
        for (int e = 0; e < 128; e += 4) {
            float4 u0 = *(const float4*)&sm[OFF_U + n0 * 128 + e];
            float4 u1 = *(const float4*)&sm[OFF_U + n1 * 128 + e];
            float u0a[4] = {u0.x, u0.y, u0.z, u0.w};
            float u1a[4] = {u1.x, u1.y, u1.z, u1.w};
#pragma unroll
            for (int c = 0; c < 4; ++c) {
                ulonglong2 w = *(const ulonglong2*)&sm[OFF_W2 + (e + c) * 64 + td * 4];
                unsigned long long d0 = dup2(u0a[c]), d1 = dup2(u1a[c]);
                ffma2(a00, d0, w.x); ffma2(a01, d0, w.y);
                ffma2(a10, d1, w.x); ffma2(a11, d1, w.y);
            }
        }
        {
            float4 b2v = *(const float4*)&sm[OFF_B2 + k * 64 + td * 4];
            float2 p00 = unpk(a00), p01 = unpk(a01), p10 = unpk(a10), p11 = unpk(a11);
            *(float4*)&sm[OFF_YB + n0 * 64 + td * 4] =
                make_float4(p00.x + b2v.x, p00.y + b2v.y, p01.x + b2v.z, p01.y + b2v.w);
            *(float4*)&sm[OFF_YB + n1 * 64 + td * 4] =
                make_float4(p10.x + b2v.x, p10.y + b2v.y, p11.x + b2v.z, p11.y + b2v.w);
        }
        __syncthreads();
        // per-(token,comp) LayerNorm over 64, write to g_Y
        for (int rr = 0; rr < 4; ++rr) {
            int n = wid * 4 + rr;
            float y0 = sm[OFF_YB + n * 64 + lane];
            float y1 = sm[OFF_YB + n * 64 + 32 + lane];
            float mu = wsum(y0 + y1) * (1.0f / 64.0f);
            float e0 = y0 - mu, e1 = y1 - mu;
            float var = wsum(e0 * e0 + e1 * e1) * (1.0f / 64.0f);
            float rstd = rsqrtf(var + 1e-5f);
            float o0 = e0 * rstd * sm[OFF_CG + k * 64 + lane]      + sm[OFF_CB + k * 64 + lane];
            float o1 = e1 * rstd * sm[OFF_CG + k * 64 + 32 + lane] + sm[OFF_CB + k * 64 + 32 + lane];
            float* Yr = g_Y + (base_tok + n) * (long)CDd + k * 64;
            Yr[lane] = o0;
            Yr[32 + lane] = o1;
        }
    }
}

// ================= K2: projection GEMM + gated residual =================
// out[m][col] = x[m][col] + gatesig[col] * (Y[m,:] @ Wp[:,col] + bp[col])
__global__ void __launch_bounds__(256)
proj_kernel(const float* __restrict__ Wp, const float* __restrict__ bp,
            const float* __restrict__ x, float* __restrict__ out)
{
    __shared__ __align__(16) float Ys[16][132];   // padded to dodge transpose bank conflicts
    __shared__ __align__(16) float Wps[16][128];
    const int tid = threadIdx.x;
    const int tn = tid & 15, tm = tid >> 4;
    const long m0 = (long)blockIdx.y * 128;
    const int nn0 = blockIdx.x * 128;

    unsigned long long acc[8][4];
#pragma unroll
    for (int m = 0; m < 8; ++m)
#pragma unroll
        for (int c = 0; c < 4; ++c) acc[m][c] = 0ull;

    for (int kc = 0; kc < 32; ++kc) {
        // Y tile -> transposed smem [k][m]
#pragma unroll
        for (int i = 0; i < 2; ++i) {
            int s = tid + i * 256;
            int m = s >> 2, kq = s & 3;
            float4 v = *(const float4*)(g_Y + (m0 + m) * (long)CDd + kc * 16 + kq * 4);
            Ys[kq * 4 + 0][m] = v.x;
            Ys[kq * 4 + 1][m] = v.y;
            Ys[kq * 4 + 2][m] = v.z;
            Ys[kq * 4 + 3][m] = v.w;
        }
        // Wp tile [k][n]
#pragma unroll
        for (int i = 0; i < 2; ++i) {
            int s = tid + i * 256;
            int kk = s >> 5, nq = s & 31;
            *(float4*)&Wps[kk][nq * 4] = *(const float4*)(Wp + (kc * 16 + kk) * (long)Dd + nn0 + nq * 4);
        }
        __syncthreads();
#pragma unroll
        for (int kk = 0; kk < 16; ++kk) {
            float4 A0 = *(const float4*)&Ys[kk][tm * 8];
            float4 A1 = *(const float4*)&Ys[kk][tm * 8 + 4];
            ulonglong2 W0 = *(const ulonglong2*)&Wps[kk][tn * 8];
            ulonglong2 W1v = *(const ulonglong2*)&Wps[kk][tn * 8 + 4];
            float av[8] = {A0.x, A0.y, A0.z, A0.w, A1.x, A1.y, A1.z, A1.w};
#pragma unroll
            for (int m = 0; m < 8; ++m) {
                unsigned long long ad = dup2(av[m]);
                ffma2(acc[m][0], ad, W0.x);
                ffma2(acc[m][1], ad, W0.y);
                ffma2(acc[m][2], ad, W1v.x);
                ffma2(acc[m][3], ad, W1v.y);
            }
        }
        __syncthreads();
    }

    // epilogue: gated residual
    const int col = nn0 + tn * 8;
    float4 gs0 = *(const float4*)&g_gatesig[col];
    float4 gs1 = *(const float4*)&g_gatesig[col + 4];
    float4 bp0 = *(const float4*)(bp + col);
    float4 bp1 = *(const float4*)(bp + col + 4);
#pragma unroll
    for (int m = 0; m < 8; ++m) {
        long row = m0 + tm * 8 + m;
        const float* xr = x + row * (long)Dd + col;
        float4 xv0 = *(const float4*)xr;
        float4 xv1 = *(const float4*)(xr + 4);
        float2 p0 = unpk(acc[m][0]), p1 = unpk(acc[m][1]);
        float2 p2 = unpk(acc[m][2]), p3 = unpk(acc[m][3]);
        float4 o0 = make_float4(xv0.x + gs0.x * (p0.x + bp0.x),
                                xv0.y + gs0.y * (p0.y + bp0.y),
                                xv0.z + gs0.z * (p1.x + bp0.z),
                                xv0.w + gs0.w * (p1.y + bp0.w));
        float4 o1 = make_float4(xv1.x + gs1.x * (p2.x + bp1.x),
                                xv1.y + gs1.y * (p2.y + bp1.y),
                                xv1.z + gs1.z * (p3.x + bp1.z),
                                xv1.w + gs1.w * (p3.y + bp1.w));
        float* orow = out + row * (long)Dd + col;
        *(float4*)orow = o0;
        *(float4*)(orow + 4) = o1;
    }
}

// ================= launch =================
extern "C" void kernel_launch(void* const* d_in, const int* in_sizes, int n_in,
                              void* d_out, int out_size) {
    const float* x       = (const float*)d_in[0];
    const float* anchors = (const float*)d_in[1];
    const float* ln_g    = (const float*)d_in[2];
    const float* ln_b    = (const float*)d_in[3];
    const float* W1      = (const float*)d_in[4];
    const float* b1      = (const float*)d_in[5];
    const float* W2      = (const float*)d_in[6];
    const float* b2      = (const float*)d_in[7];
    const float* cg      = (const float*)d_in[8];
    const float* cb      = (const float*)d_in[9];
    const float* Wp      = (const float*)d_in[10];
    const float* bp      = (const float*)d_in[11];
    const float* gate    = (const float*)d_in[12];
    float* out = (float*)d_out;

    const int Ntok = in_sizes[0] / Dd;   // 32768

    cudaFuncSetAttribute(token_kernel, cudaFuncAttributeMaxDynamicSharedMemorySize,
                         SM_FLOATS * sizeof(float));

    prep_kernel<<<Aa + 1, 256>>>(anchors, gate);
    token_kernel<<<Ntok / TB, 256, SM_FLOATS * sizeof(float)>>>(
        x, ln_g, ln_b, W1, b1, W2, b2, cg, cb);
    proj_kernel<<<dim3(8, Ntok / 128), 256>>>(Wp, bp, x, out);
}

// round 2
// speedup vs baseline: 2.9004x; 2.9004x over previous
#include <cuda_runtime.h>
#include <cuda_bf16.h>
#include <math.h>

// Problem constants (fixed shapes)
#define Dd 1024
#define Aa 16
#define Cc 8
#define DCc 64
#define CDd 512      // C*dc
#define E2 128       // 2*dc
#define TB 32        // tokens per CTA in token_kernel
#define NMAX 32768

// -------- device scratch (no allocations allowed) --------
__device__ __align__(16) float g_an[Aa * Dd];                  // l2-normalized anchors
__device__ __align__(16) float g_gatesig[Dd];                  // sigmoid(gate)
__device__ __align__(16) __nv_bfloat16 g_Yb[(size_t)NMAX * CDd]; // 32 MB: y_flat (bf16)
__device__ __align__(16) __nv_bfloat16 g_Wpb[CDd * Dd];        // Wp in bf16

// -------- f32x2 packed helpers (Blackwell) --------
__device__ __forceinline__ void ffma2(unsigned long long &d, unsigned long long a, unsigned long long b) {
    asm("fma.rn.f32x2 %0, %1, %2, %0;" : "+l"(d) : "l"(a), "l"(b));
}
__device__ __forceinline__ unsigned long long dup2(float v) {
    unsigned long long r; asm("mov.b64 %0, {%1, %1};" : "=l"(r) : "f"(v)); return r;
}
__device__ __forceinline__ float2 unpk(unsigned long long v) {
    float2 r; asm("mov.b64 {%0, %1}, %2;" : "=f"(r.x), "=f"(r.y) : "l"(v)); return r;
}

__device__ __forceinline__ float wsum(float v) {
#pragma unroll
    for (int o = 16; o; o >>= 1) v += __shfl_xor_sync(0xffffffffu, v, o);
    return v;
}

// -------- tensor-core helpers --------
__device__ __forceinline__ void ldm_x4(unsigned* r, unsigned addr) {
    asm volatile("ldmatrix.sync.aligned.m8n8.x4.shared.b16 {%0,%1,%2,%3}, [%4];"
        : "=r"(r[0]), "=r"(r[1]), "=r"(r[2]), "=r"(r[3]) : "r"(addr));
}
__device__ __forceinline__ void ldm_x4_t(unsigned* r, unsigned addr) {
    asm volatile("ldmatrix.sync.aligned.m8n8.x4.trans.shared.b16 {%0,%1,%2,%3}, [%4];"
        : "=r"(r[0]), "=r"(r[1]), "=r"(r[2]), "=r"(r[3]) : "r"(addr));
}
__device__ __forceinline__ void mma_bf16(float* d, const unsigned* a, unsigned b0, unsigned b1) {
    asm volatile("mma.sync.aligned.m16n8k16.row.col.f32.bf16.bf16.f32 "
        "{%0,%1,%2,%3}, {%4,%5,%6,%7}, {%8,%9}, {%0,%1,%2,%3};"
        : "+f"(d[0]), "+f"(d[1]), "+f"(d[2]), "+f"(d[3])
        : "r"(a[0]), "r"(a[1]), "r"(a[2]), "r"(a[3]), "r"(b0), "r"(b1));
}
__device__ __forceinline__ void cpa16(unsigned saddr, const void* g) {
    asm volatile("cp.async.cg.shared.global [%0], [%1], 16;" :: "r"(saddr), "l"(g));
}
#define CP_COMMIT() asm volatile("cp.async.commit_group;")
#define CP_WAIT0()  asm volatile("cp.async.wait_group 0;")

// ================= K0: prep anchors + gate + Wp->bf16 =================
__global__ void prep_kernel(const float* __restrict__ anchors, const float* __restrict__ gate,
                            const float* __restrict__ Wp) {
    int tid = threadIdx.x, lane = tid & 31, wid = tid >> 5;
    __shared__ float red[8];
    if (blockIdx.x < Aa) {
        int j = blockIdx.x;
        float4 v = *(const float4*)(anchors + j * Dd + tid * 4);
        float s = v.x * v.x + v.y * v.y + v.z * v.z + v.w * v.w;
        s = wsum(s);
        if (lane == 0) red[wid] = s;
        __syncthreads();
        if (wid == 0) {
            float t = (lane < 8) ? red[lane] : 0.f;
            t = wsum(t);
            if (lane == 0) red[0] = t;
        }
        __syncthreads();
        float inv = 1.0f / fmaxf(sqrtf(red[0]), 1e-12f);
        float4 o = make_float4(v.x * inv, v.y * inv, v.z * inv, v.w * inv);
        *(float4*)(g_an + j * Dd + tid * 4) = o;
    } else if (blockIdx.x == Aa) {
        for (int i = tid; i < Dd; i += 256)
            g_gatesig[i] = 1.0f / (1.0f + expf(-gate[i]));
    } else {
        // Wp -> bf16: 64 blocks, 8192 elems each
        int base = (blockIdx.x - Aa - 1) * 8192;
#pragma unroll
        for (int j = 0; j < 8; ++j) {
            int pos = base + (tid + j * 256) * 4;
            float4 v = *(const float4*)(Wp + pos);
            __nv_bfloat162 lo = __floats2bfloat162_rn(v.x, v.y);
            __nv_bfloat162 hi = __floats2bfloat162_rn(v.z, v.w);
            *(__nv_bfloat162*)(g_Wpb + pos)     = lo;
            *(__nv_bfloat162*)(g_Wpb + pos + 2) = hi;
        }
    }
}

// ================= K1: per-token LN/L2/dots + per-comp MLP + LN =================
#define OFF_AN   0        // phase A: 16384 (anchors) ; phase B reuses this region:
#define OFF_W2   0        //   8192  (W2[k] 128x64)
#define OFF_U    8192     //   4096  (u 32x128)
#define OFF_YB   12288    //   2048  (y 32x64)
#define OFF_W1   16384    //   2048
#define OFF_B1   18432    //   1024
#define OFF_B2   19456    //   512
#define OFF_CG   19968    //   512
#define OFF_CB   20480    //   512
#define OFF_TRI  20992    //   512 (32x16)
#define OFF_LNG  21504    //   1024
#define OFF_LNB  22528    //   1024
#define SM_FLOATS 23552   // 94208 bytes

__global__ void __launch_bounds__(256, 2)
token_kernel(const float* __restrict__ x,
             const float* __restrict__ ln_g, const float* __restrict__ ln_b,
             const float* __restrict__ W1, const float* __restrict__ b1,
             const float* __restrict__ W2, const float* __restrict__ b2,
             const float* __restrict__ cg, const float* __restrict__ cb)
{
    extern __shared__ float sm[];
    const int tid = threadIdx.x, lane = tid & 31, wid = tid >> 5;

    for (int t = tid; t < 4096; t += 256)
        *(float4*)&sm[OFF_AN + t * 4] = *(const float4*)&g_an[t * 4];
    for (int t = tid; t < 512; t += 256)
        *(float4*)&sm[OFF_W1 + t * 4] = *(const float4*)&W1[t * 4];
    *(float4*)&sm[OFF_B1 + tid * 4] = *(const float4*)&b1[tid * 4];
    if (tid < 128) {
        *(float4*)&sm[OFF_B2 + tid * 4] = *(const float4*)&b2[tid * 4];
        *(float4*)&sm[OFF_CG + tid * 4] = *(const float4*)&cg[tid * 4];
        *(float4*)&sm[OFF_CB + tid * 4] = *(const float4*)&cb[tid * 4];
    }
    *(float4*)&sm[OFF_LNG + tid * 4] = *(const float4*)&ln_g[tid * 4];
    *(float4*)&sm[OFF_LNB + tid * 4] = *(const float4*)&ln_b[tid * 4];
    __syncthreads();

    const long base_tok = (long)blockIdx.x * TB;

    // ---------- Phase A: warp-per-token LN + L2 + 16 anchor dots ----------
    for (int r = 0; r < TB / 8; ++r) {
        const int n = r * 8 + wid;
        const float* xr = x + (base_tok + n) * (long)Dd;
        float v[32];
#pragma unroll
        for (int q = 0; q < 8; ++q) {
            float4 t4 = *(const float4*)(xr + q * 128 + lane * 4);
            v[q * 4 + 0] = t4.x; v[q * 4 + 1] = t4.y; v[q * 4 + 2] = t4.z; v[q * 4 + 3] = t4.w;
        }
        float s = 0.f;
#pragma unroll
        for (int i = 0; i < 32; ++i) s += v[i];
        s = wsum(s);
        const float mu = s * (1.0f / Dd);
        float vs = 0.f;
#pragma unroll
        for (int i = 0; i < 32; ++i) { float dd = v[i] - mu; vs += dd * dd; }
        vs = wsum(vs);
        const float rstd = rsqrtf(vs * (1.0f / Dd) + 1e-5f);
        float n2 = 0.f;
#pragma unroll
        for (int q = 0; q < 8; ++q) {
            float4 gv = *(const float4*)&sm[OFF_LNG + q * 128 + lane * 4];
            float4 bv = *(const float4*)&sm[OFF_LNB + q * 128 + lane * 4];
            float a0 = (v[q*4+0] - mu) * rstd * gv.x + bv.x;
            float a1 = (v[q*4+1] - mu) * rstd * gv.y + bv.y;
            float a2 = (v[q*4+2] - mu) * rstd * gv.z + bv.z;
            float a3 = (v[q*4+3] - mu) * rstd * gv.w + bv.w;
            v[q*4+0] = a0; v[q*4+1] = a1; v[q*4+2] = a2; v[q*4+3] = a3;
            n2 += a0 * a0 + a1 * a1 + a2 * a2 + a3 * a3;
        }
        n2 = wsum(n2);
        const float inv = 1.0f / fmaxf(sqrtf(n2), 1e-12f);
        float acc[16];
#pragma unroll
        for (int j = 0; j < 16; ++j) acc[j] = 0.f;
#pragma unroll
        for (int q = 0; q < 8; ++q) {
#pragma unroll
            for (int j = 0; j < 16; ++j) {
                float4 a4 = *(const float4*)&sm[OFF_AN + j * Dd + q * 128 + lane * 4];
                acc[j] += v[q*4+0] * a4.x + v[q*4+1] * a4.y + v[q*4+2] * a4.z + v[q*4+3] * a4.w;
            }
        }
#pragma unroll
        for (int j = 0; j < 16; ++j) {
            float aj = wsum(acc[j]);
            if (lane == 0) sm[OFF_TRI + n * 16 + j] = 1.0f - aj * inv;
        }
    }

    // ---------- Phase B: per-compartment MLP + y-GEMM + per-comp LN ----------
    const int td = tid & 15;
    const int tpair = tid >> 4;

    for (int k = 0; k < Cc; ++k) {
        __syncthreads();
        const float4* w2g = (const float4*)(W2 + k * (E2 * DCc));
        for (int t = tid; t < 2048; t += 256)
            *(float4*)&sm[OFF_W2 + t * 4] = w2g[t];
        for (int t = tid; t < TB * E2; t += 256) {
            int n = t >> 7, e = t & 127;
            float uu = sm[OFF_TRI + n * 16 + k]     * sm[OFF_W1 + (k * 2 + 0) * E2 + e]
                     + sm[OFF_TRI + n * 16 + 8 + k] * sm[OFF_W1 + (k * 2 + 1) * E2 + e]
                     + sm[OFF_B1 + k * E2 + e];
            uu = fmaxf(uu, 0.0f);
            sm[OFF_U + t] = uu * uu;
        }
        __syncthreads();
        const int n0 = 2 * tpair, n1 = n0 + 1;
        unsigned long long a00 = 0ull, a01 = 0ull, a10 = 0ull, a11 = 0ull;
#pragma unroll 4
        for (int e = 0; e < 128; e += 4) {
            float4 u0 = *(const float4*)&sm[OFF_U + n0 * 128 + e];
            float4 u1 = *(const float4*)&sm[OFF_U + n1 * 128 + e];
            float u0a[4] = {u0.x, u0.y, u0.z, u0.w};
            float u1a[4] = {u1.x, u1.y, u1.z, u1.w};
#pragma unroll
            for (int c = 0; c < 4; ++c) {
                ulonglong2 w = *(const ulonglong2*)&sm[OFF_W2 + (e + c) * 64 + td * 4];
                unsigned long long d0 = dup2(u0a[c]), d1 = dup2(u1a[c]);
                ffma2(a00, d0, w.x); ffma2(a01, d0, w.y);
                ffma2(a10, d1, w.x); ffma2(a11, d1, w.y);
            }
        }
        {
            float4 b2v = *(const float4*)&sm[OFF_B2 + k * 64 + td * 4];
            float2 p00 = unpk(a00), p01 = unpk(a01), p10 = unpk(a10), p11 = unpk(a11);
            *(float4*)&sm[OFF_YB + n0 * 64 + td * 4] =
                make_float4(p00.x + b2v.x, p00.y + b2v.y, p01.x + b2v.z, p01.y + b2v.w);
            *(float4*)&sm[OFF_YB + n1 * 64 + td * 4] =
                make_float4(p10.x + b2v.x, p10.y + b2v.y, p11.x + b2v.z, p11.y + b2v.w);
        }
        __syncthreads();
        for (int rr = 0; rr < 4; ++rr) {
            int n = wid * 4 + rr;
            float y0 = sm[OFF_YB + n * 64 + lane];
            float y1 = sm[OFF_YB + n * 64 + 32 + lane];
            float mu = wsum(y0 + y1) * (1.0f / 64.0f);
            float e0 = y0 - mu, e1 = y1 - mu;
            float var = wsum(e0 * e0 + e1 * e1) * (1.0f / 64.0f);
            float rstd = rsqrtf(var + 1e-5f);
            float o0 = e0 * rstd * sm[OFF_CG + k * 64 + lane]      + sm[OFF_CB + k * 64 + lane];
            float o1 = e1 * rstd * sm[OFF_CG + k * 64 + 32 + lane] + sm[OFF_CB + k * 64 + 32 + lane];
            // shuffle-pack into coalesced bf16x2 stores (col = 2*lane)
            int src = 2 * (lane & 15);
            float e00 = __shfl_sync(0xffffffffu, o0, src);
            float e01 = __shfl_sync(0xffffffffu, o0, src + 1);
            float f00 = __shfl_sync(0xffffffffu, o1, src);
            float f01 = __shfl_sync(0xffffffffu, o1, src + 1);
            __nv_bfloat162 pk = (lane < 16) ? __floats2bfloat162_rn(e00, e01)
                                            : __floats2bfloat162_rn(f00, f01);
            __nv_bfloat16* Yr = g_Yb + (base_tok + n) * (long)CDd + k * 64;
            *(__nv_bfloat162*)(Yr + 2 * lane) = pk;
        }
    }
}

// ================= K2: bf16 HMMA projection GEMM + gated residual =================
// out[m][n] = x[m][n] + gatesig[n] * (Y[m,:] @ Wp[:,n] + bp[n])
// CTA tile 128x128, K-chunk 64, double-buffered cp.async, 8 warps (4Mx2N), warp 32x64.
__global__ void __launch_bounds__(256)
proj_kernel(const float* __restrict__ bp, const float* __restrict__ x, float* __restrict__ out)
{
    extern __shared__ char psm[];
    const unsigned sbase = (unsigned)__cvta_generic_to_shared(psm);
    const unsigned sA = sbase;           // 2 x 16KB (A: 128 rows x 128B)
    const unsigned sB = sbase + 32768;   // 2 x 16KB (B: 64 rows x 256B)
    const int tid = threadIdx.x, lane = tid & 31, wid = tid >> 5;
    const int wm = wid >> 1, wn = wid & 1;
    const long m0 = (long)blockIdx.y * 128;
    const int n0 = blockIdx.x * 128;

    float acc[2][8][4];
#pragma unroll
    for (int mt = 0; mt < 2; ++mt)
#pragma unroll
        for (int nt = 0; nt < 8; ++nt)
#pragma unroll
            for (int c = 0; c < 4; ++c) acc[mt][nt][c] = 0.f;

    // load-lane constants
    const int ar = tid >> 3, acq = tid & 7;        // A: row base, 16B col
    const int br = tid >> 4, bcq = tid & 15;       // B: row base, 16B col
    const __nv_bfloat16* Agbase = g_Yb + (m0 + ar) * (long)CDd + acq * 8;
    const __nv_bfloat16* Bgbase = g_Wpb + (long)br * Dd + n0 + bcq * 8;

    auto loadTile = [&](int kc, int buf) {
        unsigned Ab = sA + buf * 16384;
        unsigned Bb = sB + buf * 16384;
        const __nv_bfloat16* Ag = Agbase + kc * 64;
        const __nv_bfloat16* Bg = Bgbase + (long)(kc * 64) * Dd;
#pragma unroll
        for (int i = 0; i < 4; ++i) {
            int r = ar + i * 32;
            unsigned off = (unsigned)(r * 128 + acq * 16);
            cpa16(Ab + (off ^ ((r & 7) << 4)), Ag + (long)i * 32 * CDd);
        }
#pragma unroll
        for (int i = 0; i < 4; ++i) {
            int r = br + i * 16;
            unsigned off = (unsigned)(r * 256 + bcq * 16);
            cpa16(Bb + (off ^ ((r & 7) << 4)), Bg + (long)i * 16 * Dd);
        }
    };

    loadTile(0, 0);
    CP_COMMIT();

    const unsigned sw = (unsigned)((lane & 7) << 4);   // swizzle XOR (row&7 == lane&7 in all frags)
    const int al = lane & 15, ah = lane >> 4;

    for (int kc = 0; kc < 8; ++kc) {
        CP_WAIT0();
        __syncthreads();
        if (kc + 1 < 8) { loadTile(kc + 1, (kc + 1) & 1); CP_COMMIT(); }

        unsigned Ab = sA + (kc & 1) * 16384;
        unsigned Bb = sB + (kc & 1) * 16384;
#pragma unroll
        for (int ks = 0; ks < 4; ++ks) {
            unsigned afr[2][4];
#pragma unroll
            for (int mt = 0; mt < 2; ++mt) {
                unsigned row = wm * 32 + mt * 16 + al;
                unsigned off = row * 128 + ks * 32 + ah * 16;
                ldm_x4(afr[mt], Ab + (off ^ sw));
            }
            unsigned bfr[4][4];
#pragma unroll
            for (int nq = 0; nq < 4; ++nq) {
                unsigned row = ks * 16 + al;
                unsigned off = row * 256 + (wn * 64 + nq * 16 + ah * 8) * 2;
                ldm_x4_t(bfr[nq], Bb + (off ^ sw));
            }
#pragma unroll
            for (int mt = 0; mt < 2; ++mt)
#pragma unroll
                for (int nq = 0; nq < 4; ++nq) {
                    mma_bf16(acc[mt][2 * nq],     afr[mt], bfr[nq][0], bfr[nq][1]);
                    mma_bf16(acc[mt][2 * nq + 1], afr[mt], bfr[nq][2], bfr[nq][3]);
                }
        }
        __syncthreads();
    }

    // epilogue: gated residual, direct float2 stores
#pragma unroll
    for (int mt = 0; mt < 2; ++mt) {
        long row = m0 + wm * 32 + mt * 16 + (lane >> 2);
#pragma unroll
        for (int nt = 0; nt < 8; ++nt) {
            int col = n0 + wn * 64 + nt * 8 + 2 * (lane & 3);
            float2 gs = *(const float2*)&g_gatesig[col];
            float2 bpv = *(const float2*)(bp + col);
            // rows: row (d0,d1) and row+8 (d2,d3)
            float2 xv0 = *(const float2*)(x + row * Dd + col);
            float2 xv1 = *(const float2*)(x + (row + 8) * Dd + col);
            float2 o0, o1;
            o0.x = xv0.x + gs.x * (acc[mt][nt][0] + bpv.x);
            o0.y = xv0.y + gs.y * (acc[mt][nt][1] + bpv.y);
            o1.x = xv1.x + gs.x * (acc[mt][nt][2] + bpv.x);
            o1.y = xv1.y + gs.y * (acc[mt][nt][3] + bpv.y);
            *(float2*)(out + row * Dd + col) = o0;
            *(float2*)(out + (row + 8) * Dd + col) = o1;
        }
    }
}

// ================= launch =================
extern "C" void kernel_launch(void* const* d_in, const int* in_sizes, int n_in,
                              void* d_out, int out_size) {
    const float* x       = (const float*)d_in[0];
    const float* anchors = (const float*)d_in[1];
    const float* ln_g    = (const float*)d_in[2];
    const float* ln_b    = (const float*)d_in[3];
    const float* W1      = (const float*)d_in[4];
    const float* b1      = (const float*)d_in[5];
    const float* W2      = (const float*)d_in[6];
    const float* b2      = (const float*)d_in[7];
    const float* cg      = (const float*)d_in[8];
    const float* cb      = (const float*)d_in[9];
    const float* Wp      = (const float*)d_in[10];
    const float* bp      = (const float*)d_in[11];
    const float* gate    = (const float*)d_in[12];
    float* out = (float*)d_out;

    const int Ntok = in_sizes[0] / Dd;   // 32768

    cudaFuncSetAttribute(token_kernel, cudaFuncAttributeMaxDynamicSharedMemorySize,
                         SM_FLOATS * sizeof(float));
    cudaFuncSetAttribute(proj_kernel, cudaFuncAttributeMaxDynamicSharedMemorySize, 65536);

    prep_kernel<<<Aa + 1 + 64, 256>>>(anchors, gate, Wp);
    token_kernel<<<Ntok / TB, 256, SM_FLOATS * sizeof(float)>>>(
        x, ln_g, ln_b, W1, b1, W2, b2, cg, cb);
    proj_kernel<<<dim3(Dd / 128, Ntok / 128), 256, 65536>>>(bp, x, out);
}

// round 3
// speedup vs baseline: 4.8641x; 1.6771x over previous
#include <cuda_runtime.h>
#include <cuda_bf16.h>
#include <math.h>

// Problem constants (fixed shapes)
#define Dd 1024
#define Aa 16
#define Cc 8
#define DCc 64
#define CDd 512      // C*dc
#define E2 128       // 2*dc
#define TB 32        // tokens per CTA in token_kernel
#define NMAX 32768

// -------- device scratch (no allocations allowed) --------
__device__ __align__(16) float g_an[Aa * Dd];                    // l2-normalized anchors
__device__ __align__(16) float g_gatesig[Dd];                    // sigmoid(gate)
__device__ __align__(16) __nv_bfloat16 g_Yb[(size_t)NMAX * CDd]; // 32 MB: y_flat (bf16)
__device__ __align__(16) __nv_bfloat16 g_Wpb[CDd * Dd];          // Wp in bf16
__device__ __align__(16) uint2 g_W2frag[Cc * 8 * 8 * 32];        // W2 in HMMA B-fragment layout

__device__ __forceinline__ float wsum(float v) {
#pragma unroll
    for (int o = 16; o; o >>= 1) v += __shfl_xor_sync(0xffffffffu, v, o);
    return v;
}

// -------- tensor-core helpers --------
__device__ __forceinline__ void ldm_x4(unsigned* r, unsigned addr) {
    asm volatile("ldmatrix.sync.aligned.m8n8.x4.shared.b16 {%0,%1,%2,%3}, [%4];"
        : "=r"(r[0]), "=r"(r[1]), "=r"(r[2]), "=r"(r[3]) : "r"(addr));
}
__device__ __forceinline__ void ldm_x4_t(unsigned* r, unsigned addr) {
    asm volatile("ldmatrix.sync.aligned.m8n8.x4.trans.shared.b16 {%0,%1,%2,%3}, [%4];"
        : "=r"(r[0]), "=r"(r[1]), "=r"(r[2]), "=r"(r[3]) : "r"(addr));
}
__device__ __forceinline__ void mma_bf16(float* d, const unsigned* a, unsigned b0, unsigned b1) {
    asm volatile("mma.sync.aligned.m16n8k16.row.col.f32.bf16.bf16.f32 "
        "{%0,%1,%2,%3}, {%4,%5,%6,%7}, {%8,%9}, {%0,%1,%2,%3};"
        : "+f"(d[0]), "+f"(d[1]), "+f"(d[2]), "+f"(d[3])
        : "r"(a[0]), "r"(a[1]), "r"(a[2]), "r"(a[3]), "r"(b0), "r"(b1));
}
__device__ __forceinline__ void cpa16(unsigned saddr, const void* g) {
    asm volatile("cp.async.cg.shared.global [%0], [%1], 16;" :: "r"(saddr), "l"(g));
}
#define CP_COMMIT() asm volatile("cp.async.commit_group;")
#define CP_WAIT0()  asm volatile("cp.async.wait_group 0;")

__device__ __forceinline__ unsigned pk_bf16x2(float lo, float hi) {
    __nv_bfloat162 t = __floats2bfloat162_rn(lo, hi);
    return *reinterpret_cast<unsigned*>(&t);
}

// ================= K0: prep anchors + gate + Wp->bf16 + W2 fragments =================
__global__ void prep_kernel(const float* __restrict__ anchors, const float* __restrict__ gate,
                            const float* __restrict__ Wp, const float* __restrict__ W2) {
    int tid = threadIdx.x, lane = tid & 31, wid = tid >> 5;
    __shared__ float red[8];
    if (blockIdx.x < Aa) {
        int j = blockIdx.x;
        float4 v = *(const float4*)(anchors + j * Dd + tid * 4);
        float s = v.x * v.x + v.y * v.y + v.z * v.z + v.w * v.w;
        s = wsum(s);
        if (lane == 0) red[wid] = s;
        __syncthreads();
        if (wid == 0) {
            float t = (lane < 8) ? red[lane] : 0.f;
            t = wsum(t);
            if (lane == 0) red[0] = t;
        }
        __syncthreads();
        float inv = 1.0f / fmaxf(sqrtf(red[0]), 1e-12f);
        float4 o = make_float4(v.x * inv, v.y * inv, v.z * inv, v.w * inv);
        *(float4*)(g_an + j * Dd + tid * 4) = o;
    } else if (blockIdx.x == Aa) {
        for (int i = tid; i < Dd; i += 256)
            g_gatesig[i] = 1.0f / (1.0f + expf(-gate[i]));
    } else if (blockIdx.x < Aa + 1 + 64) {
        int base = (blockIdx.x - Aa - 1) * 8192;
#pragma unroll
        for (int j = 0; j < 8; ++j) {
            int pos = base + (tid + j * 256) * 4;
            float4 v = *(const float4*)(Wp + pos);
            __nv_bfloat162 lo = __floats2bfloat162_rn(v.x, v.y);
            __nv_bfloat162 hi = __floats2bfloat162_rn(v.z, v.w);
            *(__nv_bfloat162*)(g_Wpb + pos)     = lo;
            *(__nv_bfloat162*)(g_Wpb + pos + 2) = hi;
        }
    } else {
        // W2 -> HMMA B-fragment layout, one block per comp
        int k = blockIdx.x - (Aa + 1 + 64);
        const float* w = W2 + (long)k * E2 * DCc;   // [128][64]
        for (int idx = tid; idx < 2048; idx += 256) {
            int kt = idx >> 8;
            int rem = idx & 255;
            int nt = rem >> 5;
            int ln = rem & 31;
            int q = ln & 3, gg = ln >> 2;
            int N = nt * 8 + gg;
            int e0 = kt * 16 + 2 * q;
            uint2 val;
            val.x = pk_bf16x2(w[e0 * 64 + N],       w[(e0 + 1) * 64 + N]);
            val.y = pk_bf16x2(w[(e0 + 8) * 64 + N], w[(e0 + 9) * 64 + N]);
            g_W2frag[((k * 8 + kt) * 8 + nt) * 32 + ln] = val;
        }
    }
}

// ================= K1: per-token LN/L2/dots + warp-per-comp HMMA MLP =================
#define OFF_AN   0        // 16384 (anchors, phase A only)
#define OFF_W1   16384    //   2048
#define OFF_B1   18432    //   1024
#define OFF_B2   19456    //   512
#define OFF_CG   19968    //   512
#define OFF_CB   20480    //   512
#define OFF_TRI  20992    //   512 (32x16)
#define OFF_LNG  21504    //   1024
#define OFF_LNB  22528    //   1024
#define SM_FLOATS 23552   // 94208 bytes

__global__ void __launch_bounds__(256, 2)
token_kernel(const float* __restrict__ x,
             const float* __restrict__ ln_g, const float* __restrict__ ln_b,
             const float* __restrict__ W1, const float* __restrict__ b1,
             const float* __restrict__ b2, const float* __restrict__ cg,
             const float* __restrict__ cb)
{
    extern __shared__ float sm[];
    const int tid = threadIdx.x, lane = tid & 31, wid = tid >> 5;

    for (int t = tid; t < 4096; t += 256)
        *(float4*)&sm[OFF_AN + t * 4] = *(const float4*)&g_an[t * 4];
    for (int t = tid; t < 512; t += 256)
        *(float4*)&sm[OFF_W1 + t * 4] = *(const float4*)&W1[t * 4];
    *(float4*)&sm[OFF_B1 + tid * 4] = *(const float4*)&b1[tid * 4];
    if (tid < 128) {
        *(float4*)&sm[OFF_B2 + tid * 4] = *(const float4*)&b2[tid * 4];
        *(float4*)&sm[OFF_CG + tid * 4] = *(const float4*)&cg[tid * 4];
        *(float4*)&sm[OFF_CB + tid * 4] = *(const float4*)&cb[tid * 4];
    }
    *(float4*)&sm[OFF_LNG + tid * 4] = *(const float4*)&ln_g[tid * 4];
    *(float4*)&sm[OFF_LNB + tid * 4] = *(const float4*)&ln_b[tid * 4];
    __syncthreads();

    const long base_tok = (long)blockIdx.x * TB;

    // ---------- Phase A: warp-per-token LN + L2 + 16 anchor dots ----------
    for (int r = 0; r < TB / 8; ++r) {
        const int n = r * 8 + wid;
        const float* xr = x + (base_tok + n) * (long)Dd;
        float v[32];
#pragma unroll
        for (int q = 0; q < 8; ++q) {
            float4 t4 = *(const float4*)(xr + q * 128 + lane * 4);
            v[q * 4 + 0] = t4.x; v[q * 4 + 1] = t4.y; v[q * 4 + 2] = t4.z; v[q * 4 + 3] = t4.w;
        }
        float s = 0.f;
#pragma unroll
        for (int i = 0; i < 32; ++i) s += v[i];
        s = wsum(s);
        const float mu = s * (1.0f / Dd);
        float vs = 0.f;
#pragma unroll
        for (int i = 0; i < 32; ++i) { float dd = v[i] - mu; vs += dd * dd; }
        vs = wsum(vs);
        const float rstd = rsqrtf(vs * (1.0f / Dd) + 1e-5f);
        float n2 = 0.f;
#pragma unroll
        for (int q = 0; q < 8; ++q) {
            float4 gv = *(const float4*)&sm[OFF_LNG + q * 128 + lane * 4];
            float4 bv = *(const float4*)&sm[OFF_LNB + q * 128 + lane * 4];
            float a0 = (v[q*4+0] - mu) * rstd * gv.x + bv.x;
            float a1 = (v[q*4+1] - mu) * rstd * gv.y + bv.y;
            float a2 = (v[q*4+2] - mu) * rstd * gv.z + bv.z;
            float a3 = (v[q*4+3] - mu) * rstd * gv.w + bv.w;
            v[q*4+0] = a0; v[q*4+1] = a1; v[q*4+2] = a2; v[q*4+3] = a3;
            n2 += a0 * a0 + a1 * a1 + a2 * a2 + a3 * a3;
        }
        n2 = wsum(n2);
        const float inv = 1.0f / fmaxf(sqrtf(n2), 1e-12f);
        float acc[16];
#pragma unroll
        for (int j = 0; j < 16; ++j) acc[j] = 0.f;
#pragma unroll
        for (int q = 0; q < 8; ++q) {
#pragma unroll
            for (int j = 0; j < 16; ++j) {
                float4 a4 = *(const float4*)&sm[OFF_AN + j * Dd + q * 128 + lane * 4];
                acc[j] += v[q*4+0] * a4.x + v[q*4+1] * a4.y + v[q*4+2] * a4.z + v[q*4+3] * a4.w;
            }
        }
#pragma unroll
        for (int j = 0; j < 16; ++j) {
            float aj = wsum(acc[j]);
            if (lane == 0) sm[OFF_TRI + n * 16 + j] = 1.0f - aj * inv;
        }
    }
    __syncthreads();

    // ---------- Phase B: warp w = compartment w ----------
    {
        const int k = wid;
        const int q = lane & 3, rr = lane >> 2;

        float g00[2], g01[2], g10[2], g11[2];
#pragma unroll
        for (int mt = 0; mt < 2; ++mt) {
            int n0 = mt * 16 + rr;
            g00[mt] = sm[OFF_TRI + n0 * 16 + k];
            g01[mt] = sm[OFF_TRI + n0 * 16 + 8 + k];
            g10[mt] = sm[OFF_TRI + (n0 + 8) * 16 + k];
            g11[mt] = sm[OFF_TRI + (n0 + 8) * 16 + 8 + k];
        }

        float acc[2][8][4];
#pragma unroll
        for (int mt = 0; mt < 2; ++mt)
#pragma unroll
            for (int nt = 0; nt < 8; ++nt)
#pragma unroll
                for (int c = 0; c < 4; ++c) acc[mt][nt][c] = 0.f;

        const float* W1a = &sm[OFF_W1 + (k * 2 + 0) * E2];
        const float* W1b = &sm[OFF_W1 + (k * 2 + 1) * E2];
        const float* B1  = &sm[OFF_B1 + k * E2];

#pragma unroll
        for (int kt = 0; kt < 8; ++kt) {
            const int e0 = kt * 16 + 2 * q;
            float wa0 = W1a[e0], wa1 = W1a[e0+1], wa8 = W1a[e0+8], wa9 = W1a[e0+9];
            float wb0 = W1b[e0], wb1 = W1b[e0+1], wb8 = W1b[e0+8], wb9 = W1b[e0+9];
            float bb0 = B1[e0],  bb1 = B1[e0+1],  bb8 = B1[e0+8],  bb9 = B1[e0+9];

            unsigned afr[2][4];
#pragma unroll
            for (int mt = 0; mt < 2; ++mt) {
                float a0 = g00[mt], a1 = g01[mt], c0 = g10[mt], c1 = g11[mt];
                float t;
                t = fmaxf(a0*wa0 + a1*wb0 + bb0, 0.f); float u00 = t*t;
                t = fmaxf(a0*wa1 + a1*wb1 + bb1, 0.f); float u01 = t*t;
                t = fmaxf(a0*wa8 + a1*wb8 + bb8, 0.f); float u08 = t*t;
                t = fmaxf(a0*wa9 + a1*wb9 + bb9, 0.f); float u09 = t*t;
                t = fmaxf(c0*wa0 + c1*wb0 + bb0, 0.f); float u10 = t*t;
                t = fmaxf(c0*wa1 + c1*wb1 + bb1, 0.f); float u11 = t*t;
                t = fmaxf(c0*wa8 + c1*wb8 + bb8, 0.f); float u18 = t*t;
                t = fmaxf(c0*wa9 + c1*wb9 + bb9, 0.f); float u19 = t*t;
                afr[mt][0] = pk_bf16x2(u00, u01);
                afr[mt][1] = pk_bf16x2(u10, u11);
                afr[mt][2] = pk_bf16x2(u08, u09);
                afr[mt][3] = pk_bf16x2(u18, u19);
            }
            const uint2* Bf = &g_W2frag[((k * 8 + kt) * 8) * 32 + lane];
#pragma unroll
            for (int nt = 0; nt < 8; ++nt) {
                uint2 b = Bf[nt * 32];
                mma_bf16(acc[0][nt], afr[0], b.x, b.y);
                mma_bf16(acc[1][nt], afr[1], b.x, b.y);
            }
        }

        const float* B2 = &sm[OFF_B2 + k * 64];
        const float* CG = &sm[OFF_CG + k * 64];
        const float* CB = &sm[OFF_CB + k * 64];
#pragma unroll
        for (int mt = 0; mt < 2; ++mt) {
            float s0 = 0.f, s1 = 0.f;
#pragma unroll
            for (int nt = 0; nt < 8; ++nt) {
                float2 b2v = *(const float2*)&B2[nt * 8 + 2 * q];
                acc[mt][nt][0] += b2v.x; acc[mt][nt][1] += b2v.y;
                acc[mt][nt][2] += b2v.x; acc[mt][nt][3] += b2v.y;
                s0 += acc[mt][nt][0] + acc[mt][nt][1];
                s1 += acc[mt][nt][2] + acc[mt][nt][3];
            }
            s0 += __shfl_xor_sync(0xffffffffu, s0, 1);
            s0 += __shfl_xor_sync(0xffffffffu, s0, 2);
            s1 += __shfl_xor_sync(0xffffffffu, s1, 1);
            s1 += __shfl_xor_sync(0xffffffffu, s1, 2);
            float mu0 = s0 * (1.0f / 64.0f), mu1 = s1 * (1.0f / 64.0f);
            float v0 = 0.f, v1 = 0.f;
#pragma unroll
            for (int nt = 0; nt < 8; ++nt) {
                float d0 = acc[mt][nt][0] - mu0, d1 = acc[mt][nt][1] - mu0;
                float d2 = acc[mt][nt][2] - mu1, d3 = acc[mt][nt][3] - mu1;
                v0 += d0 * d0 + d1 * d1;
                v1 += d2 * d2 + d3 * d3;
            }
            v0 += __shfl_xor_sync(0xffffffffu, v0, 1);
            v0 += __shfl_xor_sync(0xffffffffu, v0, 2);
            v1 += __shfl_xor_sync(0xffffffffu, v1, 1);
            v1 += __shfl_xor_sync(0xffffffffu, v1, 2);
            float r0 = rsqrtf(v0 * (1.0f / 64.0f) + 1e-5f);
            float r1 = rsqrtf(v1 * (1.0f / 64.0f) + 1e-5f);

            long n0 = base_tok + mt * 16 + rr;
            __nv_bfloat16* y0 = g_Yb + n0 * (long)CDd + k * 64;
            __nv_bfloat16* y1 = y0 + 8 * (long)CDd;
#pragma unroll
            for (int nt = 0; nt < 8; ++nt) {
                int col = nt * 8 + 2 * q;
                float2 cgv = *(const float2*)&CG[col];
                float2 cbv = *(const float2*)&CB[col];
                unsigned p0 = pk_bf16x2((acc[mt][nt][0] - mu0) * r0 * cgv.x + cbv.x,
                                        (acc[mt][nt][1] - mu0) * r0 * cgv.y + cbv.y);
                unsigned p1 = pk_bf16x2((acc[mt][nt][2] - mu1) * r1 * cgv.x + cbv.x,
                                        (acc[mt][nt][3] - mu1) * r1 * cgv.y + cbv.y);
                *(unsigned*)(y0 + col) = p0;
                *(unsigned*)(y1 + col) = p1;
            }
        }
    }
}

// ================= K2: bf16 HMMA projection GEMM + gated residual =================
__global__ void __launch_bounds__(256)
proj_kernel(const float* __restrict__ bp, const float* __restrict__ x, float* __restrict__ out)
{
    extern __shared__ char psm[];
    const unsigned sbase = (unsigned)__cvta_generic_to_shared(psm);
    const unsigned sA = sbase;
    const unsigned sB = sbase + 32768;
    const int tid = threadIdx.x, lane = tid & 31, wid = tid >> 5;
    const int wm = wid >> 1, wn = wid & 1;
    const long m0 = (long)blockIdx.y * 128;
    const int n0 = blockIdx.x * 128;

    float acc[2][8][4];
#pragma unroll
    for (int mt = 0; mt < 2; ++mt)
#pragma unroll
        for (int nt = 0; nt < 8; ++nt)
#pragma unroll
            for (int c = 0; c < 4; ++c) acc[mt][nt][c] = 0.f;

    const int ar = tid >> 3, acq = tid & 7;
    const int br = tid >> 4, bcq = tid & 15;
    const __nv_bfloat16* Agbase = g_Yb + (m0 + ar) * (long)CDd + acq * 8;
    const __nv_bfloat16* Bgbase = g_Wpb + (long)br * Dd + n0 + bcq * 8;

    auto loadTile = [&](int kc, int buf) {
        unsigned Ab = sA + buf * 16384;
        unsigned Bb = sB + buf * 16384;
        const __nv_bfloat16* Ag = Agbase + kc * 64;
        const __nv_bfloat16* Bg = Bgbase + (long)(kc * 64) * Dd;
#pragma unroll
        for (int i = 0; i < 4; ++i) {
            int r = ar + i * 32;
            unsigned off = (unsigned)(r * 128 + acq * 16);
            cpa16(Ab + (off ^ ((r & 7) << 4)), Ag + (long)i * 32 * CDd);
        }
#pragma unroll
        for (int i = 0; i < 4; ++i) {
            int r = br + i * 16;
            unsigned off = (unsigned)(r * 256 + bcq * 16);
            cpa16(Bb + (off ^ ((r & 7) << 4)), Bg + (long)i * 16 * Dd);
        }
    };

    loadTile(0, 0);
    CP_COMMIT();

    const unsigned sw = (unsigned)((lane & 7) << 4);
    const int al = lane & 15, ah = lane >> 4;

    for (int kc = 0; kc < 8; ++kc) {
        CP_WAIT0();
        __syncthreads();
        if (kc + 1 < 8) { loadTile(kc + 1, (kc + 1) & 1); CP_COMMIT(); }

        unsigned Ab = sA + (kc & 1) * 16384;
        unsigned Bb = sB + (kc & 1) * 16384;
#pragma unroll
        for (int ks = 0; ks < 4; ++ks) {
            unsigned afr[2][4];
#pragma unroll
            for (int mt = 0; mt < 2; ++mt) {
                unsigned row = wm * 32 + mt * 16 + al;
                unsigned off = row * 128 + ks * 32 + ah * 16;
                ldm_x4(afr[mt], Ab + (off ^ sw));
            }
            unsigned bfr[4][4];
#pragma unroll
            for (int nq = 0; nq < 4; ++nq) {
                unsigned row = ks * 16 + al;
                unsigned off = row * 256 + (wn * 64 + nq * 16 + ah * 8) * 2;
                ldm_x4_t(bfr[nq], Bb + (off ^ sw));
            }
#pragma unroll
            for (int mt = 0; mt < 2; ++mt)
#pragma unroll
                for (int nq = 0; nq < 4; ++nq) {
                    mma_bf16(acc[mt][2 * nq],     afr[mt], bfr[nq][0], bfr[nq][1]);
                    mma_bf16(acc[mt][2 * nq + 1], afr[mt], bfr[nq][2], bfr[nq][3]);
                }
        }
        __syncthreads();
    }

#pragma unroll
    for (int mt = 0; mt < 2; ++mt) {
        long row = m0 + wm * 32 + mt * 16 + (lane >> 2);
#pragma unroll
        for (int nt = 0; nt < 8; ++nt) {
            int col = n0 + wn * 64 + nt * 8 + 2 * (lane & 3);
            float2 gs = *(const float2*)&g_gatesig[col];
            float2 bpv = *(const float2*)(bp + col);
            float2 xv0 = *(const float2*)(x + row * Dd + col);
            float2 xv1 = *(const float2*)(x + (row + 8) * Dd + col);
            float2 o0, o1;
            o0.x = xv0.x + gs.x * (acc[mt][nt][0] + bpv.x);
            o0.y = xv0.y + gs.y * (acc[mt][nt][1] + bpv.y);
            o1.x = xv1.x + gs.x * (acc[mt][nt][2] + bpv.x);
            o1.y = xv1.y + gs.y * (acc[mt][nt][3] + bpv.y);
            *(float2*)(out + row * Dd + col) = o0;
            *(float2*)(out + (row + 8) * Dd + col) = o1;
        }
    }
}

// ================= launch =================
extern "C" void kernel_launch(void* const* d_in, const int* in_sizes, int n_in,
                              void* d_out, int out_size) {
    const float* x       = (const float*)d_in[0];
    const float* anchors = (const float*)d_in[1];
    const float* ln_g    = (const float*)d_in[2];
    const float* ln_b    = (const float*)d_in[3];
    const float* W1      = (const float*)d_in[4];
    const float* b1      = (const float*)d_in[5];
    const float* W2      = (const float*)d_in[6];
    const float* b2      = (const float*)d_in[7];
    const float* cg      = (const float*)d_in[8];
    const float* cb      = (const float*)d_in[9];
    const float* Wp      = (const float*)d_in[10];
    const float* bp      = (const float*)d_in[11];
    const float* gate    = (const float*)d_in[12];
    float* out = (float*)d_out;

    const int Ntok = in_sizes[0] / Dd;   // 32768

    cudaFuncSetAttribute(token_kernel, cudaFuncAttributeMaxDynamicSharedMemorySize,
                         SM_FLOATS * sizeof(float));
    cudaFuncSetAttribute(proj_kernel, cudaFuncAttributeMaxDynamicSharedMemorySize, 65536);

    prep_kernel<<<Aa + 1 + 64 + Cc, 256>>>(anchors, gate, Wp, W2);
    token_kernel<<<Ntok / TB, 256, SM_FLOATS * sizeof(float)>>>(
        x, ln_g, ln_b, W1, b1, b2, cg, cb);
    proj_kernel<<<dim3(Dd / 128, Ntok / 128), 256, 65536>>>(bp, x, out);
}

// round 4
// speedup vs baseline: 6.2371x; 1.2823x over previous
#include <cuda_runtime.h>
#include <cuda_bf16.h>
#include <math.h>

// Problem constants (fixed shapes)
#define Dd 1024
#define Aa 16
#define Cc 8
#define DCc 64
#define CDd 512      // C*dc
#define E2 128       // 2*dc
#define TB 32        // tokens per CTA in token_kernel
#define NMAX 32768

// -------- device scratch (no allocations allowed) --------
__device__ __align__(16) float g_an[Aa * Dd];                    // l2-normalized anchors
__device__ __align__(16) float g_gatesig[Dd];                    // sigmoid(gate)
__device__ __align__(16) __nv_bfloat16 g_Yb[(size_t)NMAX * CDd]; // 32 MB: y_flat (bf16)
__device__ __align__(16) __nv_bfloat16 g_Wpb[CDd * Dd];          // Wp in bf16
__device__ __align__(16) uint2 g_W2frag[Cc * 8 * 8 * 32];        // W2 in HMMA B-fragment layout
__device__ __align__(16) uint2 g_AnFrag[64 * 2 * 32];            // anchors in HMMA B-fragment layout

__device__ __forceinline__ float wsum(float v) {
#pragma unroll
    for (int o = 16; o; o >>= 1) v += __shfl_xor_sync(0xffffffffu, v, o);
    return v;
}

// -------- tensor-core helpers --------
__device__ __forceinline__ void ldm_x4(unsigned* r, unsigned addr) {
    asm volatile("ldmatrix.sync.aligned.m8n8.x4.shared.b16 {%0,%1,%2,%3}, [%4];"
        : "=r"(r[0]), "=r"(r[1]), "=r"(r[2]), "=r"(r[3]) : "r"(addr));
}
__device__ __forceinline__ void ldm_x4_t(unsigned* r, unsigned addr) {
    asm volatile("ldmatrix.sync.aligned.m8n8.x4.trans.shared.b16 {%0,%1,%2,%3}, [%4];"
        : "=r"(r[0]), "=r"(r[1]), "=r"(r[2]), "=r"(r[3]) : "r"(addr));
}
__device__ __forceinline__ void mma_bf16(float* d, const unsigned* a, unsigned b0, unsigned b1) {
    asm volatile("mma.sync.aligned.m16n8k16.row.col.f32.bf16.bf16.f32 "
        "{%0,%1,%2,%3}, {%4,%5,%6,%7}, {%8,%9}, {%0,%1,%2,%3};"
        : "+f"(d[0]), "+f"(d[1]), "+f"(d[2]), "+f"(d[3])
        : "r"(a[0]), "r"(a[1]), "r"(a[2]), "r"(a[3]), "r"(b0), "r"(b1));
}
__device__ __forceinline__ void cpa16(unsigned saddr, const void* g) {
    asm volatile("cp.async.cg.shared.global [%0], [%1], 16;" :: "r"(saddr), "l"(g));
}
#define CP_COMMIT() asm volatile("cp.async.commit_group;")
#define CP_WAIT0()  asm volatile("cp.async.wait_group 0;")

__device__ __forceinline__ unsigned pk_bf16x2(float lo, float hi) {
    __nv_bfloat162 t = __floats2bfloat162_rn(lo, hi);
    return *reinterpret_cast<unsigned*>(&t);
}

// ================= K0: prep anchors + gate + Wp->bf16 + W2 fragments =================
__global__ void prep_kernel(const float* __restrict__ anchors, const float* __restrict__ gate,
                            const float* __restrict__ Wp, const float* __restrict__ W2) {
    int tid = threadIdx.x, lane = tid & 31, wid = tid >> 5;
    __shared__ float red[8];
    if (blockIdx.x < Aa) {
        int j = blockIdx.x;
        float4 v = *(const float4*)(anchors + j * Dd + tid * 4);
        float s = v.x * v.x + v.y * v.y + v.z * v.z + v.w * v.w;
        s = wsum(s);
        if (lane == 0) red[wid] = s;
        __syncthreads();
        if (wid == 0) {
            float t = (lane < 8) ? red[lane] : 0.f;
            t = wsum(t);
            if (lane == 0) red[0] = t;
        }
        __syncthreads();
        float inv = 1.0f / fmaxf(sqrtf(red[0]), 1e-12f);
        float4 o = make_float4(v.x * inv, v.y * inv, v.z * inv, v.w * inv);
        *(float4*)(g_an + j * Dd + tid * 4) = o;
    } else if (blockIdx.x == Aa) {
        for (int i = tid; i < Dd; i += 256)
            g_gatesig[i] = 1.0f / (1.0f + expf(-gate[i]));
    } else if (blockIdx.x < Aa + 1 + 64) {
        int base = (blockIdx.x - Aa - 1) * 8192;
#pragma unroll
        for (int j = 0; j < 8; ++j) {
            int pos = base + (tid + j * 256) * 4;
            float4 v = *(const float4*)(Wp + pos);
            __nv_bfloat162 lo = __floats2bfloat162_rn(v.x, v.y);
            __nv_bfloat162 hi = __floats2bfloat162_rn(v.z, v.w);
            *(__nv_bfloat162*)(g_Wpb + pos)     = lo;
            *(__nv_bfloat162*)(g_Wpb + pos + 2) = hi;
        }
    } else {
        // W2 -> HMMA B-fragment layout, one block per comp
        int k = blockIdx.x - (Aa + 1 + 64);
        const float* w = W2 + (long)k * E2 * DCc;   // [128][64]
        for (int idx = tid; idx < 2048; idx += 256) {
            int kt = idx >> 8;
            int rem = idx & 255;
            int nt = rem >> 5;
            int ln = rem & 31;
            int q = ln & 3, gg = ln >> 2;
            int N = nt * 8 + gg;
            int e0 = kt * 16 + 2 * q;
            uint2 val;
            val.x = pk_bf16x2(w[e0 * 64 + N],       w[(e0 + 1) * 64 + N]);
            val.y = pk_bf16x2(w[(e0 + 8) * 64 + N], w[(e0 + 9) * 64 + N]);
            g_W2frag[((k * 8 + kt) * 8 + nt) * 32 + ln] = val;
        }
    }
}

// ================= K0b: anchor B-fragment table (needs normalized g_an) =================
__global__ void prep2_kernel() {
    int idx = blockIdx.x * 256 + threadIdx.x;   // grid 4 x 256 = 1024
    for (int e = idx; e < 64 * 2 * 32; e += 1024) {
        int ln = e & 31, nt = (e >> 5) & 1, kt = e >> 6;
        int q = ln & 3, gg = ln >> 2;
        int n = nt * 8 + gg;
        int k0 = kt * 16 + 2 * q;
        uint2 val;
        val.x = pk_bf16x2(g_an[n * Dd + k0],     g_an[n * Dd + k0 + 1]);
        val.y = pk_bf16x2(g_an[n * Dd + k0 + 8], g_an[n * Dd + k0 + 9]);
        g_AnFrag[(kt * 2 + nt) * 32 + ln] = val;
    }
}

// ================= K1: LN/L2 -> bf16 H -> HMMA dots -> warp-per-comp HMMA MLP =================
// smem layout (floats):
#define OFF_H    0        // 16384 floats = 64 KB: H tile 32 x 1024 bf16 (row stride 2048 B, swizzled)
#define OFF_W1   16384    //   2048
#define OFF_B1   18432    //   1024
#define OFF_B2   19456    //   512
#define OFF_CG   19968    //   512
#define OFF_CB   20480    //   512
#define OFF_TRI  20992    //   512 (32x16)
#define OFF_LNG  21504    //   1024
#define OFF_LNB  22528    //   1024
#define OFF_PART 23552    //   2048 (4 kq x 32 tok x 16 anch)
#define SM_FLOATS 25600   // 102400 bytes

__global__ void __launch_bounds__(256, 2)
token_kernel(const float* __restrict__ x,
             const float* __restrict__ ln_g, const float* __restrict__ ln_b,
             const float* __restrict__ W1, const float* __restrict__ b1,
             const float* __restrict__ b2, const float* __restrict__ cg,
             const float* __restrict__ cb)
{
    extern __shared__ float sm[];
    const unsigned sbase = (unsigned)__cvta_generic_to_shared(sm);
    const int tid = threadIdx.x, lane = tid & 31, wid = tid >> 5;

    for (int t = tid; t < 512; t += 256)
        *(float4*)&sm[OFF_W1 + t * 4] = *(const float4*)&W1[t * 4];
    *(float4*)&sm[OFF_B1 + tid * 4] = *(const float4*)&b1[tid * 4];
    if (tid < 128) {
        *(float4*)&sm[OFF_B2 + tid * 4] = *(const float4*)&b2[tid * 4];
        *(float4*)&sm[OFF_CG + tid * 4] = *(const float4*)&cg[tid * 4];
        *(float4*)&sm[OFF_CB + tid * 4] = *(const float4*)&cb[tid * 4];
    }
    *(float4*)&sm[OFF_LNG + tid * 4] = *(const float4*)&ln_g[tid * 4];
    *(float4*)&sm[OFF_LNB + tid * 4] = *(const float4*)&ln_b[tid * 4];
    __syncthreads();

    const long base_tok = (long)blockIdx.x * TB;

    // ---------- Phase A: warp-per-token LN + L2, store normalized h (bf16, swizzled) ----------
    for (int r = 0; r < TB / 8; ++r) {
        const int n = r * 8 + wid;
        const float* xr = x + (base_tok + n) * (long)Dd;
        float v[32];
#pragma unroll
        for (int q = 0; q < 8; ++q) {
            float4 t4 = *(const float4*)(xr + q * 128 + lane * 4);
            v[q * 4 + 0] = t4.x; v[q * 4 + 1] = t4.y; v[q * 4 + 2] = t4.z; v[q * 4 + 3] = t4.w;
        }
        float s = 0.f;
#pragma unroll
        for (int i = 0; i < 32; ++i) s += v[i];
        s = wsum(s);
        const float mu = s * (1.0f / Dd);
        float vs = 0.f;
#pragma unroll
        for (int i = 0; i < 32; ++i) { float dd = v[i] - mu; vs += dd * dd; }
        vs = wsum(vs);
        const float rstd = rsqrtf(vs * (1.0f / Dd) + 1e-5f);
        float n2 = 0.f;
#pragma unroll
        for (int q = 0; q < 8; ++q) {
            float4 gv = *(const float4*)&sm[OFF_LNG + q * 128 + lane * 4];
            float4 bv = *(const float4*)&sm[OFF_LNB + q * 128 + lane * 4];
            float a0 = (v[q*4+0] - mu) * rstd * gv.x + bv.x;
            float a1 = (v[q*4+1] - mu) * rstd * gv.y + bv.y;
            float a2 = (v[q*4+2] - mu) * rstd * gv.z + bv.z;
            float a3 = (v[q*4+3] - mu) * rstd * gv.w + bv.w;
            v[q*4+0] = a0; v[q*4+1] = a1; v[q*4+2] = a2; v[q*4+3] = a3;
            n2 += a0 * a0 + a1 * a1 + a2 * a2 + a3 * a3;
        }
        n2 = wsum(n2);
        const float inv = 1.0f / fmaxf(sqrtf(n2), 1e-12f);

        // store h*inv as bf16 into H tile (row n, stride 2048 B, XOR-swizzled)
        char* hrow = (char*)sm + n * 2048;
        const unsigned swz = (unsigned)((n & 7) << 4);
#pragma unroll
        for (int q = 0; q < 8; ++q) {
            unsigned p0 = pk_bf16x2(v[q*4+0] * inv, v[q*4+1] * inv);
            unsigned p1 = pk_bf16x2(v[q*4+2] * inv, v[q*4+3] * inv);
            unsigned off = (unsigned)(q * 256 + lane * 8) ^ swz;
            *(uint2*)(hrow + off) = make_uint2(p0, p1);
        }
    }
    __syncthreads();

    // ---------- Phase A2: tri = 1 - H @ Anchors^T via HMMA ----------
    {
        const int mt = wid & 1;          // m-tile (16 tokens)
        const int kq = wid >> 1;         // k-quarter (256 dims)
        const int al = lane & 15, ah = lane >> 4;
        const unsigned rowb = (unsigned)(mt * 16 + al);
        const unsigned rowoff = rowb * 2048;
        const unsigned swz = (rowb & 7) << 4;

        float acc[2][4];
#pragma unroll
        for (int nt = 0; nt < 2; ++nt)
#pragma unroll
            for (int c = 0; c < 4; ++c) acc[nt][c] = 0.f;

#pragma unroll
        for (int s = 0; s < 16; ++s) {
            const int kt = kq * 16 + s;
            unsigned afr[4];
            unsigned off = rowoff + (((unsigned)(kt * 32 + ah * 16)) ^ swz);
            ldm_x4(afr, sbase + off);
            uint2 b0 = g_AnFrag[(kt * 2 + 0) * 32 + lane];
            uint2 b1 = g_AnFrag[(kt * 2 + 1) * 32 + lane];
            mma_bf16(acc[0], afr, b0.x, b0.y);
            mma_bf16(acc[1], afr, b1.x, b1.y);
        }
        // write partial dots
        float* P = &sm[OFF_PART + kq * 512];
        const int r0 = mt * 16 + (lane >> 2);
        const int c0 = 2 * (lane & 3);
        P[r0 * 16 + c0]           = acc[0][0];
        P[r0 * 16 + c0 + 1]       = acc[0][1];
        P[(r0 + 8) * 16 + c0]     = acc[0][2];
        P[(r0 + 8) * 16 + c0 + 1] = acc[0][3];
        P[r0 * 16 + 8 + c0]           = acc[1][0];
        P[r0 * 16 + 8 + c0 + 1]       = acc[1][1];
        P[(r0 + 8) * 16 + 8 + c0]     = acc[1][2];
        P[(r0 + 8) * 16 + 8 + c0 + 1] = acc[1][3];
    }
    __syncthreads();
    for (int t = tid; t < 512; t += 256) {
        float d = sm[OFF_PART + t] + sm[OFF_PART + 512 + t]
                + sm[OFF_PART + 1024 + t] + sm[OFF_PART + 1536 + t];
        sm[OFF_TRI + t] = 1.0f - d;
    }
    __syncthreads();

    // ---------- Phase B: warp w = compartment w ----------
    {
        const int k = wid;
        const int q = lane & 3, rr = lane >> 2;

        float g00[2], g01[2], g10[2], g11[2];
#pragma unroll
        for (int mt = 0; mt < 2; ++mt) {
            int n0 = mt * 16 + rr;
            g00[mt] = sm[OFF_TRI + n0 * 16 + k];
            g01[mt] = sm[OFF_TRI + n0 * 16 + 8 + k];
            g10[mt] = sm[OFF_TRI + (n0 + 8) * 16 + k];
            g11[mt] = sm[OFF_TRI + (n0 + 8) * 16 + 8 + k];
        }

        float acc[2][8][4];
#pragma unroll
        for (int mt = 0; mt < 2; ++mt)
#pragma unroll
            for (int nt = 0; nt < 8; ++nt)
#pragma unroll
                for (int c = 0; c < 4; ++c) acc[mt][nt][c] = 0.f;

        const float* W1a = &sm[OFF_W1 + (k * 2 + 0) * E2];
        const float* W1b = &sm[OFF_W1 + (k * 2 + 1) * E2];
        const float* B1  = &sm[OFF_B1 + k * E2];

#pragma unroll
        for (int kt = 0; kt < 8; ++kt) {
            const int e0 = kt * 16 + 2 * q;
            float wa0 = W1a[e0], wa1 = W1a[e0+1], wa8 = W1a[e0+8], wa9 = W1a[e0+9];
            float wb0 = W1b[e0], wb1 = W1b[e0+1], wb8 = W1b[e0+8], wb9 = W1b[e0+9];
            float bb0 = B1[e0],  bb1 = B1[e0+1],  bb8 = B1[e0+8],  bb9 = B1[e0+9];

            unsigned afr[2][4];
#pragma unroll
            for (int mt = 0; mt < 2; ++mt) {
                float a0 = g00[mt], a1 = g01[mt], c0 = g10[mt], c1 = g11[mt];
                float t;
                t = fmaxf(a0*wa0 + a1*wb0 + bb0, 0.f); float u00 = t*t;
                t = fmaxf(a0*wa1 + a1*wb1 + bb1, 0.f); float u01 = t*t;
                t = fmaxf(a0*wa8 + a1*wb8 + bb8, 0.f); float u08 = t*t;
                t = fmaxf(a0*wa9 + a1*wb9 + bb9, 0.f); float u09 = t*t;
                t = fmaxf(c0*wa0 + c1*wb0 + bb0, 0.f); float u10 = t*t;
                t = fmaxf(c0*wa1 + c1*wb1 + bb1, 0.f); float u11 = t*t;
                t = fmaxf(c0*wa8 + c1*wb8 + bb8, 0.f); float u18 = t*t;
                t = fmaxf(c0*wa9 + c1*wb9 + bb9, 0.f); float u19 = t*t;
                afr[mt][0] = pk_bf16x2(u00, u01);
                afr[mt][1] = pk_bf16x2(u10, u11);
                afr[mt][2] = pk_bf16x2(u08, u09);
                afr[mt][3] = pk_bf16x2(u18, u19);
            }
            const uint2* Bf = &g_W2frag[((k * 8 + kt) * 8) * 32 + lane];
#pragma unroll
            for (int nt = 0; nt < 8; ++nt) {
                uint2 b = Bf[nt * 32];
                mma_bf16(acc[0][nt], afr[0], b.x, b.y);
                mma_bf16(acc[1][nt], afr[1], b.x, b.y);
            }
        }

        const float* B2 = &sm[OFF_B2 + k * 64];
        const float* CG = &sm[OFF_CG + k * 64];
        const float* CB = &sm[OFF_CB + k * 64];
#pragma unroll
        for (int mt = 0; mt < 2; ++mt) {
            float s0 = 0.f, s1 = 0.f;
#pragma unroll
            for (int nt = 0; nt < 8; ++nt) {
                float2 b2v = *(const float2*)&B2[nt * 8 + 2 * q];
                acc[mt][nt][0] += b2v.x; acc[mt][nt][1] += b2v.y;
                acc[mt][nt][2] += b2v.x; acc[mt][nt][3] += b2v.y;
                s0 += acc[mt][nt][0] + acc[mt][nt][1];
                s1 += acc[mt][nt][2] + acc[mt][nt][3];
            }
            s0 += __shfl_xor_sync(0xffffffffu, s0, 1);
            s0 += __shfl_xor_sync(0xffffffffu, s0, 2);
            s1 += __shfl_xor_sync(0xffffffffu, s1, 1);
            s1 += __shfl_xor_sync(0xffffffffu, s1, 2);
            float mu0 = s0 * (1.0f / 64.0f), mu1 = s1 * (1.0f / 64.0f);
            float v0 = 0.f, v1 = 0.f;
#pragma unroll
            for (int nt = 0; nt < 8; ++nt) {
                float d0 = acc[mt][nt][0] - mu0, d1 = acc[mt][nt][1] - mu0;
                float d2 = acc[mt][nt][2] - mu1, d3 = acc[mt][nt][3] - mu1;
                v0 += d0 * d0 + d1 * d1;
                v1 += d2 * d2 + d3 * d3;
            }
            v0 += __shfl_xor_sync(0xffffffffu, v0, 1);
            v0 += __shfl_xor_sync(0xffffffffu, v0, 2);
            v1 += __shfl_xor_sync(0xffffffffu, v1, 1);
            v1 += __shfl_xor_sync(0xffffffffu, v1, 2);
            float r0 = rsqrtf(v0 * (1.0f / 64.0f) + 1e-5f);
            float r1 = rsqrtf(v1 * (1.0f / 64.0f) + 1e-5f);

            long n0 = base_tok + mt * 16 + rr;
            __nv_bfloat16* y0 = g_Yb + n0 * (long)CDd + k * 64;
            __nv_bfloat16* y1 = y0 + 8 * (long)CDd;
#pragma unroll
            for (int nt = 0; nt < 8; ++nt) {
                int col = nt * 8 + 2 * q;
                float2 cgv = *(const float2*)&CG[col];
                float2 cbv = *(const float2*)&CB[col];
                unsigned p0 = pk_bf16x2((acc[mt][nt][0] - mu0) * r0 * cgv.x + cbv.x,
                                        (acc[mt][nt][1] - mu0) * r0 * cgv.y + cbv.y);
                unsigned p1 = pk_bf16x2((acc[mt][nt][2] - mu1) * r1 * cgv.x + cbv.x,
                                        (acc[mt][nt][3] - mu1) * r1 * cgv.y + cbv.y);
                *(unsigned*)(y0 + col) = p0;
                *(unsigned*)(y1 + col) = p1;
            }
        }
    }
}

// ================= K2: bf16 HMMA projection GEMM + gated residual =================
__global__ void __launch_bounds__(256)
proj_kernel(const float* __restrict__ bp, const float* __restrict__ x, float* __restrict__ out)
{
    extern __shared__ char psm[];
    const unsigned sbase = (unsigned)__cvta_generic_to_shared(psm);
    const unsigned sA = sbase;
    const unsigned sB = sbase + 32768;
    const int tid = threadIdx.x, lane = tid & 31, wid = tid >> 5;
    const int wm = wid >> 1, wn = wid & 1;
    const long m0 = (long)blockIdx.y * 128;
    const int n0 = blockIdx.x * 128;

    float acc[2][8][4];
#pragma unroll
    for (int mt = 0; mt < 2; ++mt)
#pragma unroll
        for (int nt = 0; nt < 8; ++nt)
#pragma unroll
            for (int c = 0; c < 4; ++c) acc[mt][nt][c] = 0.f;

    const int ar = tid >> 3, acq = tid & 7;
    const int br = tid >> 4, bcq = tid & 15;
    const __nv_bfloat16* Agbase = g_Yb + (m0 + ar) * (long)CDd + acq * 8;
    const __nv_bfloat16* Bgbase = g_Wpb + (long)br * Dd + n0 + bcq * 8;

    auto loadTile = [&](int kc, int buf) {
        unsigned Ab = sA + buf * 16384;
        unsigned Bb = sB + buf * 16384;
        const __nv_bfloat16* Ag = Agbase + kc * 64;
        const __nv_bfloat16* Bg = Bgbase + (long)(kc * 64) * Dd;
#pragma unroll
        for (int i = 0; i < 4; ++i) {
            int r = ar + i * 32;
            unsigned off = (unsigned)(r * 128 + acq * 16);
            cpa16(Ab + (off ^ ((r & 7) << 4)), Ag + (long)i * 32 * CDd);
        }
#pragma unroll
        for (int i = 0; i < 4; ++i) {
            int r = br + i * 16;
            unsigned off = (unsigned)(r * 256 + bcq * 16);
            cpa16(Bb + (off ^ ((r & 7) << 4)), Bg + (long)i * 16 * Dd);
        }
    };

    loadTile(0, 0);
    CP_COMMIT();

    const unsigned sw = (unsigned)((lane & 7) << 4);
    const int al = lane & 15, ah = lane >> 4;

    for (int kc = 0; kc < 8; ++kc) {
        CP_WAIT0();
        __syncthreads();
        if (kc + 1 < 8) { loadTile(kc + 1, (kc + 1) & 1); CP_COMMIT(); }

        unsigned Ab = sA + (kc & 1) * 16384;
        unsigned Bb = sB + (kc & 1) * 16384;
#pragma unroll
        for (int ks = 0; ks < 4; ++ks) {
            unsigned afr[2][4];
#pragma unroll
            for (int mt = 0; mt < 2; ++mt) {
                unsigned row = wm * 32 + mt * 16 + al;
                unsigned off = row * 128 + ks * 32 + ah * 16;
                ldm_x4(afr[mt], Ab + (off ^ sw));
            }
            unsigned bfr[4][4];
#pragma unroll
            for (int nq = 0; nq < 4; ++nq) {
                unsigned row = ks * 16 + al;
                unsigned off = row * 256 + (wn * 64 + nq * 16 + ah * 8) * 2;
                ldm_x4_t(bfr[nq], Bb + (off ^ sw));
            }
#pragma unroll
            for (int mt = 0; mt < 2; ++mt)
#pragma unroll
                for (int nq = 0; nq < 4; ++nq) {
                    mma_bf16(acc[mt][2 * nq],     afr[mt], bfr[nq][0], bfr[nq][1]);
                    mma_bf16(acc[mt][2 * nq + 1], afr[mt], bfr[nq][2], bfr[nq][3]);
                }
        }
        __syncthreads();
    }

#pragma unroll
    for (int mt = 0; mt < 2; ++mt) {
        long row = m0 + wm * 32 + mt * 16 + (lane >> 2);
#pragma unroll
        for (int nt = 0; nt < 8; ++nt) {
            int col = n0 + wn * 64 + nt * 8 + 2 * (lane & 3);
            float2 gs = *(const float2*)&g_gatesig[col];
            float2 bpv = *(const float2*)(bp + col);
            float2 xv0 = *(const float2*)(x + row * Dd + col);
            float2 xv1 = *(const float2*)(x + (row + 8) * Dd + col);
            float2 o0, o1;
            o0.x = xv0.x + gs.x * (acc[mt][nt][0] + bpv.x);
            o0.y = xv0.y + gs.y * (acc[mt][nt][1] + bpv.y);
            o1.x = xv1.x + gs.x * (acc[mt][nt][2] + bpv.x);
            o1.y = xv1.y + gs.y * (acc[mt][nt][3] + bpv.y);
            *(float2*)(out + row * Dd + col) = o0;
            *(float2*)(out + (row + 8) * Dd + col) = o1;
        }
    }
}

// ================= launch =================
extern "C" void kernel_launch(void* const* d_in, const int* in_sizes, int n_in,
                              void* d_out, int out_size) {
    const float* x       = (const float*)d_in[0];
    const float* anchors = (const float*)d_in[1];
    const float* ln_g    = (const float*)d_in[2];
    const float* ln_b    = (const float*)d_in[3];
    const float* W1      = (const float*)d_in[4];
    const float* b1      = (const float*)d_in[5];
    const float* W2      = (const float*)d_in[6];
    const float* b2      = (const float*)d_in[7];
    const float* cg      = (const float*)d_in[8];
    const float* cb      = (const float*)d_in[9];
    const float* Wp      = (const float*)d_in[10];
    const float* bp      = (const float*)d_in[11];
    const float* gate    = (const float*)d_in[12];
    float* out = (float*)d_out;

    const int Ntok = in_sizes[0] / Dd;   // 32768

    cudaFuncSetAttribute(token_kernel, cudaFuncAttributeMaxDynamicSharedMemorySize,
                         SM_FLOATS * sizeof(float));
    cudaFuncSetAttribute(proj_kernel, cudaFuncAttributeMaxDynamicSharedMemorySize, 65536);

    prep_kernel<<<Aa + 1 + 64 + Cc, 256>>>(anchors, gate, Wp, W2);
    prep2_kernel<<<4, 256>>>();
    token_kernel<<<Ntok / TB, 256, SM_FLOATS * sizeof(float)>>>(
        x, ln_g, ln_b, W1, b1, b2, cg, cb);
    proj_kernel<<<dim3(Dd / 128, Ntok / 128), 256, 65536>>>(bp, x, out);
}

// round 6
// speedup vs baseline: 6.4185x; 1.0291x over previous
#include <cuda_runtime.h>
#include <cuda_bf16.h>
#include <math.h>

// Problem constants (fixed shapes)
#define Dd 1024
#define Aa 16
#define Cc 8
#define DCc 64
#define CDd 512      // C*dc
#define E2 128       // 2*dc
#define TB 32        // tokens per CTA in token_kernel
#define NMAX 32768

// -------- device scratch (no allocations allowed) --------
__device__ __align__(16) float g_an[Aa * Dd];                    // l2-normalized anchors
__device__ __align__(16) float g_gatesig[Dd];                    // sigmoid(gate)
__device__ __align__(16) __nv_bfloat16 g_Yb[(size_t)NMAX * CDd]; // 32 MB: y_flat (bf16)
__device__ __align__(16) __nv_bfloat16 g_Wpb[CDd * Dd];          // Wp in bf16 [k][n]
__device__ __align__(16) uint2 g_W2frag[Cc * 8 * 8 * 32];        // W2 in HMMA B-fragment layout
__device__ __align__(16) uint2 g_AnFrag[64 * 2 * 32];            // anchors in HMMA B-fragment layout

__device__ __forceinline__ float wsum(float v) {
#pragma unroll
    for (int o = 16; o; o >>= 1) v += __shfl_xor_sync(0xffffffffu, v, o);
    return v;
}

// -------- tensor-core helpers --------
__device__ __forceinline__ void ldm_x4(unsigned* r, unsigned addr) {
    asm volatile("ldmatrix.sync.aligned.m8n8.x4.shared.b16 {%0,%1,%2,%3}, [%4];"
        : "=r"(r[0]), "=r"(r[1]), "=r"(r[2]), "=r"(r[3]) : "r"(addr));
}
__device__ __forceinline__ void ldm_x4_t(unsigned* r, unsigned addr) {
    asm volatile("ldmatrix.sync.aligned.m8n8.x4.trans.shared.b16 {%0,%1,%2,%3}, [%4];"
        : "=r"(r[0]), "=r"(r[1]), "=r"(r[2]), "=r"(r[3]) : "r"(addr));
}
__device__ __forceinline__ void mma_bf16(float* d, const unsigned* a, unsigned b0, unsigned b1) {
    asm volatile("mma.sync.aligned.m16n8k16.row.col.f32.bf16.bf16.f32 "
        "{%0,%1,%2,%3}, {%4,%5,%6,%7}, {%8,%9}, {%0,%1,%2,%3};"
        : "+f"(d[0]), "+f"(d[1]), "+f"(d[2]), "+f"(d[3])
        : "r"(a[0]), "r"(a[1]), "r"(a[2]), "r"(a[3]), "r"(b0), "r"(b1));
}
__device__ __forceinline__ void cpa16(unsigned saddr, const void* g) {
    asm volatile("cp.async.cg.shared.global [%0], [%1], 16;" :: "r"(saddr), "l"(g));
}
#define CP_COMMIT() asm volatile("cp.async.commit_group;")
#define CP_WAIT0()  asm volatile("cp.async.wait_group 0;")

__device__ __forceinline__ unsigned pk_bf16x2(float lo, float hi) {
    __nv_bfloat162 t = __floats2bfloat162_rn(lo, hi);
    return *reinterpret_cast<unsigned*>(&t);
}

// ================= K0: prep anchors + gate + Wp->bf16 + W2 fragments =================
__global__ void prep_kernel(const float* __restrict__ anchors, const float* __restrict__ gate,
                            const float* __restrict__ Wp, const float* __restrict__ W2) {
    int tid = threadIdx.x, lane = tid & 31, wid = tid >> 5;
    __shared__ float red[8];
    if (blockIdx.x < Aa) {
        int j = blockIdx.x;
        float4 v = *(const float4*)(anchors + j * Dd + tid * 4);
        float s = v.x * v.x + v.y * v.y + v.z * v.z + v.w * v.w;
        s = wsum(s);
        if (lane == 0) red[wid] = s;
        __syncthreads();
        if (wid == 0) {
            float t = (lane < 8) ? red[lane] : 0.f;
            t = wsum(t);
            if (lane == 0) red[0] = t;
        }
        __syncthreads();
        float inv = 1.0f / fmaxf(sqrtf(red[0]), 1e-12f);
        float4 o = make_float4(v.x * inv, v.y * inv, v.z * inv, v.w * inv);
        *(float4*)(g_an + j * Dd + tid * 4) = o;
    } else if (blockIdx.x == Aa) {
        for (int i = tid; i < Dd; i += 256)
            g_gatesig[i] = 1.0f / (1.0f + expf(-gate[i]));
    } else if (blockIdx.x < Aa + 1 + 64) {
        int base = (blockIdx.x - Aa - 1) * 8192;
#pragma unroll
        for (int j = 0; j < 8; ++j) {
            int pos = base + (tid + j * 256) * 4;
            float4 v = *(const float4*)(Wp + pos);
            __nv_bfloat162 lo = __floats2bfloat162_rn(v.x, v.y);
            __nv_bfloat162 hi = __floats2bfloat162_rn(v.z, v.w);
            *(__nv_bfloat162*)(g_Wpb + pos)     = lo;
            *(__nv_bfloat162*)(g_Wpb + pos + 2) = hi;
        }
    } else {
        // W2 -> HMMA B-fragment layout, one block per comp
        int k = blockIdx.x - (Aa + 1 + 64);
        const float* w = W2 + (long)k * E2 * DCc;   // [128][64]
        for (int idx = tid; idx < 2048; idx += 256) {
            int kt = idx >> 8;
            int rem = idx & 255;
            int nt = rem >> 5;
            int ln = rem & 31;
            int q = ln & 3, gg = ln >> 2;
            int N = nt * 8 + gg;
            int e0 = kt * 16 + 2 * q;
            uint2 val;
            val.x = pk_bf16x2(w[e0 * 64 + N],       w[(e0 + 1) * 64 + N]);
            val.y = pk_bf16x2(w[(e0 + 8) * 64 + N], w[(e0 + 9) * 64 + N]);
            g_W2frag[((k * 8 + kt) * 8 + nt) * 32 + ln] = val;
        }
    }
}

// ================= K0b: anchor B-fragment table (needs normalized g_an) =================
__global__ void prep2_kernel() {
    int idx = blockIdx.x * 256 + threadIdx.x;   // grid 4 x 256 = 1024
    for (int e = idx; e < 64 * 2 * 32; e += 1024) {
        int ln = e & 31, nt = (e >> 5) & 1, kt = e >> 6;
        int q = ln & 3, gg = ln >> 2;
        int n = nt * 8 + gg;
        int k0 = kt * 16 + 2 * q;
        uint2 val;
        val.x = pk_bf16x2(g_an[n * Dd + k0],     g_an[n * Dd + k0 + 1]);
        val.y = pk_bf16x2(g_an[n * Dd + k0 + 8], g_an[n * Dd + k0 + 9]);
        g_AnFrag[(kt * 2 + nt) * 32 + ln] = val;
    }
}

// ================= K1: LN/L2 -> bf16 H -> HMMA dots -> warp-per-comp HMMA MLP =================
#define OFF_H    0        // 16384 floats = 64 KB: H tile 32 x 1024 bf16 (row stride 2048 B, swizzled)
#define OFF_W1   16384
#define OFF_B1   18432
#define OFF_B2   19456
#define OFF_CG   19968
#define OFF_CB   20480
#define OFF_TRI  20992
#define OFF_LNG  21504
#define OFF_LNB  22528
#define OFF_PART 23552
#define SM_FLOATS 25600   // 102400 bytes

__global__ void __launch_bounds__(256, 2)
token_kernel(const float* __restrict__ x,
             const float* __restrict__ ln_g, const float* __restrict__ ln_b,
             const float* __restrict__ W1, const float* __restrict__ b1,
             const float* __restrict__ b2, const float* __restrict__ cg,
             const float* __restrict__ cb)
{
    extern __shared__ float sm[];
    const unsigned sbase = (unsigned)__cvta_generic_to_shared(sm);
    const int tid = threadIdx.x, lane = tid & 31, wid = tid >> 5;

    for (int t = tid; t < 512; t += 256)
        *(float4*)&sm[OFF_W1 + t * 4] = *(const float4*)&W1[t * 4];
    *(float4*)&sm[OFF_B1 + tid * 4] = *(const float4*)&b1[tid * 4];
    if (tid < 128) {
        *(float4*)&sm[OFF_B2 + tid * 4] = *(const float4*)&b2[tid * 4];
        *(float4*)&sm[OFF_CG + tid * 4] = *(const float4*)&cg[tid * 4];
        *(float4*)&sm[OFF_CB + tid * 4] = *(const float4*)&cb[tid * 4];
    }
    *(float4*)&sm[OFF_LNG + tid * 4] = *(const float4*)&ln_g[tid * 4];
    *(float4*)&sm[OFF_LNB + tid * 4] = *(const float4*)&ln_b[tid * 4];
    __syncthreads();

    const long base_tok = (long)blockIdx.x * TB;

    // ---------- Phase A: warp-per-token LN + L2, store normalized h (bf16, swizzled) ----------
    for (int r = 0; r < TB / 8; ++r) {
        const int n = r * 8 + wid;
        const float* xr = x + (base_tok + n) * (long)Dd;
        float v[32];
#pragma unroll
        for (int q = 0; q < 8; ++q) {
            float4 t4 = *(const float4*)(xr + q * 128 + lane * 4);
            v[q * 4 + 0] = t4.x; v[q * 4 + 1] = t4.y; v[q * 4 + 2] = t4.z; v[q * 4 + 3] = t4.w;
        }
        float s = 0.f;
#pragma unroll
        for (int i = 0; i < 32; ++i) s += v[i];
        s = wsum(s);
        const float mu = s * (1.0f / Dd);
        float vs = 0.f;
#pragma unroll
        for (int i = 0; i < 32; ++i) { float dd = v[i] - mu; vs += dd * dd; }
        vs = wsum(vs);
        const float rstd = rsqrtf(vs * (1.0f / Dd) + 1e-5f);
        float n2 = 0.f;
#pragma unroll
        for (int q = 0; q < 8; ++q) {
            float4 gv = *(const float4*)&sm[OFF_LNG + q * 128 + lane * 4];
            float4 bv = *(const float4*)&sm[OFF_LNB + q * 128 + lane * 4];
            float a0 = (v[q*4+0] - mu) * rstd * gv.x + bv.x;
            float a1 = (v[q*4+1] - mu) * rstd * gv.y + bv.y;
            float a2 = (v[q*4+2] - mu) * rstd * gv.z + bv.z;
            float a3 = (v[q*4+3] - mu) * rstd * gv.w + bv.w;
            v[q*4+0] = a0; v[q*4+1] = a1; v[q*4+2] = a2; v[q*4+3] = a3;
            n2 += a0 * a0 + a1 * a1 + a2 * a2 + a3 * a3;
        }
        n2 = wsum(n2);
        const float inv = 1.0f / fmaxf(sqrtf(n2), 1e-12f);

        char* hrow = (char*)sm + n * 2048;
        const unsigned swz = (unsigned)((n & 7) << 4);
#pragma unroll
        for (int q = 0; q < 8; ++q) {
            unsigned p0 = pk_bf16x2(v[q*4+0] * inv, v[q*4+1] * inv);
            unsigned p1 = pk_bf16x2(v[q*4+2] * inv, v[q*4+3] * inv);
            unsigned off = (unsigned)(q * 256 + lane * 8) ^ swz;
            *(uint2*)(hrow + off) = make_uint2(p0, p1);
        }
    }
    __syncthreads();

    // ---------- Phase A2: tri = 1 - H @ Anchors^T via HMMA ----------
    {
        const int mt = wid & 1;
        const int kq = wid >> 1;
        const int al = lane & 15, ah = lane >> 4;
        const unsigned rowb = (unsigned)(mt * 16 + al);
        const unsigned rowoff = rowb * 2048;
        const unsigned swz = (rowb & 7) << 4;

        float acc[2][4];
#pragma unroll
        for (int nt = 0; nt < 2; ++nt)
#pragma unroll
            for (int c = 0; c < 4; ++c) acc[nt][c] = 0.f;

#pragma unroll
        for (int s = 0; s < 16; ++s) {
            const int kt = kq * 16 + s;
            unsigned afr[4];
            unsigned off = rowoff + (((unsigned)(kt * 32 + ah * 16)) ^ swz);
            ldm_x4(afr, sbase + off);
            uint2 b0 = g_AnFrag[(kt * 2 + 0) * 32 + lane];
            uint2 b1 = g_AnFrag[(kt * 2 + 1) * 32 + lane];
            mma_bf16(acc[0], afr, b0.x, b0.y);
            mma_bf16(acc[1], afr, b1.x, b1.y);
        }
        float* P = &sm[OFF_PART + kq * 512];
        const int r0 = mt * 16 + (lane >> 2);
        const int c0 = 2 * (lane & 3);
        P[r0 * 16 + c0]           = acc[0][0];
        P[r0 * 16 + c0 + 1]       = acc[0][1];
        P[(r0 + 8) * 16 + c0]     = acc[0][2];
        P[(r0 + 8) * 16 + c0 + 1] = acc[0][3];
        P[r0 * 16 + 8 + c0]           = acc[1][0];
        P[r0 * 16 + 8 + c0 + 1]       = acc[1][1];
        P[(r0 + 8) * 16 + 8 + c0]     = acc[1][2];
        P[(r0 + 8) * 16 + 8 + c0 + 1] = acc[1][3];
    }
    __syncthreads();
    for (int t = tid; t < 512; t += 256) {
        float d = sm[OFF_PART + t] + sm[OFF_PART + 512 + t]
                + sm[OFF_PART + 1024 + t] + sm[OFF_PART + 1536 + t];
        sm[OFF_TRI + t] = 1.0f - d;
    }
    __syncthreads();

    // ---------- Phase B: warp w = compartment w ----------
    {
        const int k = wid;
        const int q = lane & 3, rr = lane >> 2;

        float g00[2], g01[2], g10[2], g11[2];
#pragma unroll
        for (int mt = 0; mt < 2; ++mt) {
            int n0 = mt * 16 + rr;
            g00[mt] = sm[OFF_TRI + n0 * 16 + k];
            g01[mt] = sm[OFF_TRI + n0 * 16 + 8 + k];
            g10[mt] = sm[OFF_TRI + (n0 + 8) * 16 + k];
            g11[mt] = sm[OFF_TRI + (n0 + 8) * 16 + 8 + k];
        }

        float acc[2][8][4];
#pragma unroll
        for (int mt = 0; mt < 2; ++mt)
#pragma unroll
            for (int nt = 0; nt < 8; ++nt)
#pragma unroll
                for (int c = 0; c < 4; ++c) acc[mt][nt][c] = 0.f;

        const float* W1a = &sm[OFF_W1 + (k * 2 + 0) * E2];
        const float* W1b = &sm[OFF_W1 + (k * 2 + 1) * E2];
        const float* B1  = &sm[OFF_B1 + k * E2];

#pragma unroll
        for (int kt = 0; kt < 8; ++kt) {
            const int e0 = kt * 16 + 2 * q;
            float wa0 = W1a[e0], wa1 = W1a[e0+1], wa8 = W1a[e0+8], wa9 = W1a[e0+9];
            float wb0 = W1b[e0], wb1 = W1b[e0+1], wb8 = W1b[e0+8], wb9 = W1b[e0+9];
            float bb0 = B1[e0],  bb1 = B1[e0+1],  bb8 = B1[e0+8],  bb9 = B1[e0+9];

            unsigned afr[2][4];
#pragma unroll
            for (int mt = 0; mt < 2; ++mt) {
                float a0 = g00[mt], a1 = g01[mt], c0 = g10[mt], c1 = g11[mt];
                float t;
                t = fmaxf(a0*wa0 + a1*wb0 + bb0, 0.f); float u00 = t*t;
                t = fmaxf(a0*wa1 + a1*wb1 + bb1, 0.f); float u01 = t*t;
                t = fmaxf(a0*wa8 + a1*wb8 + bb8, 0.f); float u08 = t*t;
                t = fmaxf(a0*wa9 + a1*wb9 + bb9, 0.f); float u09 = t*t;
                t = fmaxf(c0*wa0 + c1*wb0 + bb0, 0.f); float u10 = t*t;
                t = fmaxf(c0*wa1 + c1*wb1 + bb1, 0.f); float u11 = t*t;
                t = fmaxf(c0*wa8 + c1*wb8 + bb8, 0.f); float u18 = t*t;
                t = fmaxf(c0*wa9 + c1*wb9 + bb9, 0.f); float u19 = t*t;
                afr[mt][0] = pk_bf16x2(u00, u01);
                afr[mt][1] = pk_bf16x2(u10, u11);
                afr[mt][2] = pk_bf16x2(u08, u09);
                afr[mt][3] = pk_bf16x2(u18, u19);
            }
            const uint2* Bf = &g_W2frag[((k * 8 + kt) * 8) * 32 + lane];
#pragma unroll
            for (int nt = 0; nt < 8; ++nt) {
                uint2 b = Bf[nt * 32];
                mma_bf16(acc[0][nt], afr[0], b.x, b.y);
                mma_bf16(acc[1][nt], afr[1], b.x, b.y);
            }
        }

        const float* B2 = &sm[OFF_B2 + k * 64];
        const float* CG = &sm[OFF_CG + k * 64];
        const float* CB = &sm[OFF_CB + k * 64];
#pragma unroll
        for (int mt = 0; mt < 2; ++mt) {
            float s0 = 0.f, s1 = 0.f;
#pragma unroll
            for (int nt = 0; nt < 8; ++nt) {
                float2 b2v = *(const float2*)&B2[nt * 8 + 2 * q];
                acc[mt][nt][0] += b2v.x; acc[mt][nt][1] += b2v.y;
                acc[mt][nt][2] += b2v.x; acc[mt][nt][3] += b2v.y;
                s0 += acc[mt][nt][0] + acc[mt][nt][1];
                s1 += acc[mt][nt][2] + acc[mt][nt][3];
            }
            s0 += __shfl_xor_sync(0xffffffffu, s0, 1);
            s0 += __shfl_xor_sync(0xffffffffu, s0, 2);
            s1 += __shfl_xor_sync(0xffffffffu, s1, 1);
            s1 += __shfl_xor_sync(0xffffffffu, s1, 2);
            float mu0 = s0 * (1.0f / 64.0f), mu1 = s1 * (1.0f / 64.0f);
            float v0 = 0.f, v1 = 0.f;
#pragma unroll
            for (int nt = 0; nt < 8; ++nt) {
                float d0 = acc[mt][nt][0] - mu0, d1 = acc[mt][nt][1] - mu0;
                float d2 = acc[mt][nt][2] - mu1, d3 = acc[mt][nt][3] - mu1;
                v0 += d0 * d0 + d1 * d1;
                v1 += d2 * d2 + d3 * d3;
            }
            v0 += __shfl_xor_sync(0xffffffffu, v0, 1);
            v0 += __shfl_xor_sync(0xffffffffu, v0, 2);
            v1 += __shfl_xor_sync(0xffffffffu, v1, 1);
            v1 += __shfl_xor_sync(0xffffffffu, v1, 2);
            float r0 = rsqrtf(v0 * (1.0f / 64.0f) + 1e-5f);
            float r1 = rsqrtf(v1 * (1.0f / 64.0f) + 1e-5f);

            long n0 = base_tok + mt * 16 + rr;
            __nv_bfloat16* y0 = g_Yb + n0 * (long)CDd + k * 64;
            __nv_bfloat16* y1 = y0 + 8 * (long)CDd;
#pragma unroll
            for (int nt = 0; nt < 8; ++nt) {
                int col = nt * 8 + 2 * q;
                float2 cgv = *(const float2*)&CG[col];
                float2 cbv = *(const float2*)&CB[col];
                unsigned p0 = pk_bf16x2((acc[mt][nt][0] - mu0) * r0 * cgv.x + cbv.x,
                                        (acc[mt][nt][1] - mu0) * r0 * cgv.y + cbv.y);
                unsigned p1 = pk_bf16x2((acc[mt][nt][2] - mu1) * r1 * cgv.x + cbv.x,
                                        (acc[mt][nt][3] - mu1) * r1 * cgv.y + cbv.y);
                *(unsigned*)(y0 + col) = p0;
                *(unsigned*)(y1 + col) = p1;
            }
        }
    }
}

// ================= K2: bf16 HMMA projection GEMM + gated residual =================
// CTA 128x128, K-chunk 64, double-buffered cp.async, 8 warps (2M x 4N), warp 64x32.
// Epilogue: smem transpose for fully coalesced x/out access.
#define PSM_TOTAL 68608   // >= max(65536 mainloop, 128*132*4=67584 epilogue)

__global__ void __launch_bounds__(256)
proj_kernel(const float* __restrict__ bp, const float* __restrict__ x, float* __restrict__ out)
{
    extern __shared__ char psm[];
    const unsigned sbase = (unsigned)__cvta_generic_to_shared(psm);
    const unsigned sA = sbase;
    const unsigned sB = sbase + 32768;
    float* smf = (float*)psm;
    const int tid = threadIdx.x, lane = tid & 31, wid = tid >> 5;
    const int wm = wid & 1, wn = wid >> 1;      // 2M x 4N
    const long m0 = (long)blockIdx.y * 128;
    const int n0 = blockIdx.x * 128;

    float acc[4][4][4];
#pragma unroll
    for (int mt = 0; mt < 4; ++mt)
#pragma unroll
        for (int nt = 0; nt < 4; ++nt)
#pragma unroll
            for (int c = 0; c < 4; ++c) acc[mt][nt][c] = 0.f;

    const int ar = tid >> 3, acq = tid & 7;
    const int br = tid >> 4, bcq = tid & 15;
    const __nv_bfloat16* Agbase = g_Yb + (m0 + ar) * (long)CDd + acq * 8;
    const __nv_bfloat16* Bgbase = g_Wpb + (long)br * Dd + n0 + bcq * 8;

    auto loadTile = [&](int kc, int buf) {
        unsigned Ab = sA + buf * 16384;
        unsigned Bb = sB + buf * 16384;
        const __nv_bfloat16* Ag = Agbase + kc * 64;
        const __nv_bfloat16* Bg = Bgbase + (long)(kc * 64) * Dd;
#pragma unroll
        for (int i = 0; i < 4; ++i) {
            int r = ar + i * 32;
            unsigned off = (unsigned)(r * 128 + acq * 16);
            cpa16(Ab + (off ^ ((r & 7) << 4)), Ag + (long)i * 32 * CDd);
        }
#pragma unroll
        for (int i = 0; i < 4; ++i) {
            int r = br + i * 16;
            unsigned off = (unsigned)(r * 256 + bcq * 16);
            cpa16(Bb + (off ^ ((r & 7) << 4)), Bg + (long)i * 16 * Dd);
        }
    };

    loadTile(0, 0);
    CP_COMMIT();

    const unsigned sw = (unsigned)((lane & 7) << 4);
    const int al = lane & 15, ah = lane >> 4;

    for (int kc = 0; kc < 8; ++kc) {
        CP_WAIT0();
        __syncthreads();
        if (kc + 1 < 8) { loadTile(kc + 1, (kc + 1) & 1); CP_COMMIT(); }

        unsigned Ab = sA + (kc & 1) * 16384;
        unsigned Bb = sB + (kc & 1) * 16384;
#pragma unroll
        for (int ks = 0; ks < 4; ++ks) {
            unsigned afr[4][4];
#pragma unroll
            for (int mt = 0; mt < 4; ++mt) {
                unsigned row = wm * 64 + mt * 16 + al;
                unsigned off = row * 128 + ks * 32 + ah * 16;
                ldm_x4(afr[mt], Ab + (off ^ sw));
            }
            unsigned bfr[2][4];
#pragma unroll
            for (int nq = 0; nq < 2; ++nq) {
                unsigned row = ks * 16 + al;
                unsigned off = row * 256 + (wn * 32 + nq * 16 + ah * 8) * 2;
                ldm_x4_t(bfr[nq], Bb + (off ^ sw));
            }
#pragma unroll
            for (int mt = 0; mt < 4; ++mt)
#pragma unroll
                for (int nq = 0; nq < 2; ++nq) {
                    mma_bf16(acc[mt][2 * nq],     afr[mt], bfr[nq][0], bfr[nq][1]);
                    mma_bf16(acc[mt][2 * nq + 1], afr[mt], bfr[nq][2], bfr[nq][3]);
                }
        }
        __syncthreads();
    }

    // stage accumulators to smem [128][132] (reuses A/B buffers; all reads done)
#pragma unroll
    for (int mt = 0; mt < 4; ++mt) {
        int r0 = wm * 64 + mt * 16 + (lane >> 2);
#pragma unroll
        for (int nt = 0; nt < 4; ++nt) {
            int c = wn * 32 + nt * 8 + 2 * (lane & 3);
            *(float2*)&smf[r0 * 132 + c]       = make_float2(acc[mt][nt][0], acc[mt][nt][1]);
            *(float2*)&smf[(r0 + 8) * 132 + c] = make_float2(acc[mt][nt][2], acc[mt][nt][3]);
        }
    }
    __syncthreads();

    // coalesced gated-residual epilogue: warp w handles rows it*8 + w, lanes cover 128 cols
    const int cc = lane * 4;
    float4 gs  = *(const float4*)&g_gatesig[n0 + cc];
    float4 bpv = *(const float4*)(bp + n0 + cc);
#pragma unroll
    for (int it = 0; it < 16; ++it) {
        int rr = it * 8 + wid;
        float4 v = *(float4*)&smf[rr * 132 + cc];
        const float* xr = x + (m0 + rr) * (long)Dd + n0 + cc;
        float4 xv = *(const float4*)xr;
        float4 o;
        o.x = xv.x + gs.x * (v.x + bpv.x);
        o.y = xv.y + gs.y * (v.y + bpv.y);
        o.z = xv.z + gs.z * (v.z + bpv.z);
        o.w = xv.w + gs.w * (v.w + bpv.w);
        *(float4*)(out + (m0 + rr) * (long)Dd + n0 + cc) = o;
    }
}

// ================= launch =================
extern "C" void kernel_launch(void* const* d_in, const int* in_sizes, int n_in,
                              void* d_out, int out_size) {
    const float* x       = (const float*)d_in[0];
    const float* anchors = (const float*)d_in[1];
    const float* ln_g    = (const float*)d_in[2];
    const float* ln_b    = (const float*)d_in[3];
    const float* W1      = (const float*)d_in[4];
    const float* b1      = (const float*)d_in[5];
    const float* W2      = (const float*)d_in[6];
    const float* b2      = (const float*)d_in[7];
    const float* cg      = (const float*)d_in[8];
    const float* cb      = (const float*)d_in[9];
    const float* Wp      = (const float*)d_in[10];
    const float* bp      = (const float*)d_in[11];
    const float* gate    = (const float*)d_in[12];
    float* out = (float*)d_out;

    const int Ntok = in_sizes[0] / Dd;   // 32768

    cudaFuncSetAttribute(token_kernel, cudaFuncAttributeMaxDynamicSharedMemorySize,
                         SM_FLOATS * sizeof(float));
    cudaFuncSetAttribute(proj_kernel, cudaFuncAttributeMaxDynamicSharedMemorySize, PSM_TOTAL);

    prep_kernel<<<Aa + 1 + 64 + Cc, 256>>>(anchors, gate, Wp, W2);
    prep2_kernel<<<4, 256>>>();
    token_kernel<<<Ntok / TB, 256, SM_FLOATS * sizeof(float)>>>(
        x, ln_g, ln_b, W1, b1, b2, cg, cb);
    proj_kernel<<<dim3(Dd / 128, Ntok / 128), 256, PSM_TOTAL>>>(bp, x, out);
}